// round 13
// baseline (speedup 1.0000x reference)
#include <cuda_runtime.h>
#include <cuda_fp16.h>
#include <cstdint>
#include <math.h>

#define BATCH 4
#define SEQ   2048
#define HID   1024
#define DIM   1024
#define SCALE 0.03125f   // 1/sqrt(1024)

// Scratch (device globals; runtime allocation is forbidden)
__device__ float  g_P [(long)BATCH * SEQ * SEQ];
__device__ __half g_Xh[(long)BATCH * SEQ * HID];
__device__ __half g_Wh[(long)3 * HID * DIM];     // Wq,Wk,Wv stacked, [H][D] each
__device__ __half g_Qh[(long)BATCH * SEQ * DIM];
__device__ __half g_Kh[(long)BATCH * SEQ * DIM];
__device__ __half g_Vh[(long)BATCH * SEQ * DIM];
__device__ __half g_Ph[(long)BATCH * SEQ * SEQ];

// ---------------------------------------------------------------------------
// PTX helpers (baseline sm_80-level PTX)
// ---------------------------------------------------------------------------
__device__ __forceinline__ uint32_t smem_u32(const void* p) {
    uint32_t a;
    asm("{ .reg .u64 t; cvta.to.shared.u64 t, %1; cvt.u32.u64 %0, t; }"
        : "=r"(a) : "l"(p));
    return a;
}
__device__ __forceinline__ void cpa16(uint32_t dst, const void* src) {
    asm volatile("cp.async.cg.shared.global [%0], [%1], 16;" :: "r"(dst), "l"(src));
}
#define CP_COMMIT() asm volatile("cp.async.commit_group;" ::: "memory")
#define CP_WAIT1()  asm volatile("cp.async.wait_group 1;" ::: "memory")

__device__ __forceinline__ void ldsm_x4(uint32_t* r, uint32_t addr) {
    asm volatile("ldmatrix.sync.aligned.m8n8.x4.shared.b16 {%0,%1,%2,%3}, [%4];"
                 : "=r"(r[0]), "=r"(r[1]), "=r"(r[2]), "=r"(r[3]) : "r"(addr));
}
__device__ __forceinline__ void ldsm_x4_t(uint32_t* r, uint32_t addr) {
    asm volatile("ldmatrix.sync.aligned.m8n8.x4.trans.shared.b16 {%0,%1,%2,%3}, [%4];"
                 : "=r"(r[0]), "=r"(r[1]), "=r"(r[2]), "=r"(r[3]) : "r"(addr));
}
__device__ __forceinline__ void mma_f16(float* c, const uint32_t* a,
                                        const uint32_t* b) {
    asm volatile(
        "mma.sync.aligned.m16n8k16.row.col.f32.f16.f16.f32 "
        "{%0,%1,%2,%3}, {%4,%5,%6,%7}, {%8,%9}, {%0,%1,%2,%3};"
        : "+f"(c[0]), "+f"(c[1]), "+f"(c[2]), "+f"(c[3])
        : "r"(a[0]), "r"(a[1]), "r"(a[2]), "r"(a[3]), "r"(b[0]), "r"(b[1]));
}

// ---------------------------------------------------------------------------
// Fused fp32 -> fp16 quantize for X, Wq, Wk, Wv in one launch.
// Index space: [0, nX + 3*nW) in float4 units.
// ---------------------------------------------------------------------------
__global__ __launch_bounds__(256)
void quant_all(const float* __restrict__ X, const float* __restrict__ Wq,
               const float* __restrict__ Wk, const float* __restrict__ Wv,
               __half* __restrict__ Xh, __half* __restrict__ Wh,
               long nX4, long nW4)
{
    long total = nX4 + 3 * nW4;
    long i = blockIdx.x * 256 + threadIdx.x;
    long stride = (long)gridDim.x * 256;
    for (; i < total; i += stride) {
        const float* src;
        __half* dst;
        long j;
        if (i < nX4) {
            src = X; dst = Xh; j = i;
        } else {
            long k = i - nX4;
            int w = (int)(k / nW4);
            j = k - (long)w * nW4;
            src = (w == 0) ? Wq : (w == 1) ? Wk : Wv;
            dst = Wh + (long)w * HID * DIM;
        }
        float4 v = *(const float4*)(src + j * 4);
        __half2 h0 = __floats2half2_rn(v.x, v.y);
        __half2 h1 = __floats2half2_rn(v.z, v.w);
        uint2 u;
        u.x = reinterpret_cast<uint32_t&>(h0);
        u.y = reinterpret_cast<uint32_t&>(h1);
        *(uint2*)(dst + j * 4) = u;
    }
}

// ---------------------------------------------------------------------------
// Tiling config: BM=BN=128, BK=32, 256 threads, 8 warps (4m x 2n),
// warp tile 32x64. 3-stage cp.async pipeline, ONE barrier per k-iter.
// ---------------------------------------------------------------------------
#define ASTR 40    // 16-bit row stride A / B(NT): 80B, ldmatrix conflict-free
#define BSTR 136   // 16-bit row stride B(NN) [k][n]: 272B, conflict-free
#define NSTG 3

template <bool TRANSB>
__device__ __forceinline__ void mma_tile1(
    float acc[2][8][4], uint32_t aS, uint32_t bS, int wm, int wn, int lane)
{
    #pragma unroll
    for (int ks = 0; ks < 2; ++ks) {
        uint32_t aF[2][4];
        #pragma unroll
        for (int mt = 0; mt < 2; ++mt) {
            uint32_t off =
                ((uint32_t)(wm + mt * 16 + (lane & 15)) * ASTR +
                 ks * 16 + (lane >> 4) * 8) * 2;
            ldsm_x4(aF[mt], aS + off);
        }
        #pragma unroll
        for (int np = 0; np < 4; ++np) {
            uint32_t bF[4];
            if (TRANSB) {
                uint32_t nrow = wn + np * 16 + (lane & 7) + (lane >> 4) * 8;
                uint32_t off = (nrow * ASTR + ks * 16 + ((lane >> 3) & 1) * 8) * 2;
                ldsm_x4(bF, bS + off);
            } else {
                uint32_t krow = ks * 16 + (lane & 15);
                uint32_t ncol = wn + np * 16 + (lane >> 4) * 8;
                uint32_t off = (krow * BSTR + ncol) * 2;
                ldsm_x4_t(bF, bS + off);
            }
            #pragma unroll
            for (int h = 0; h < 2; ++h) {
                #pragma unroll
                for (int mt = 0; mt < 2; ++mt)
                    mma_f16(acc[mt][np * 2 + h], aF[mt], bF + h * 2);
            }
        }
    }
}

#define ACC_DECL()                                                          \
    float acc[2][8][4];                                                     \
    _Pragma("unroll")                                                       \
    for (int i_ = 0; i_ < 2; ++i_)                                          \
        _Pragma("unroll")                                                   \
        for (int j_ = 0; j_ < 8; ++j_)                                      \
            _Pragma("unroll")                                               \
            for (int t_ = 0; t_ < 4; ++t_) acc[i_][j_][t_] = 0.f;

// Mainloop with a single barrier per iteration: the top-of-loop sync orders
// the previous iteration's ldsm reads of stage (s+2)%3 before this
// iteration's cp.async writes into it.
#define GEMM_MAINLOOP(KEND, ACTIVE, TRANSB_)                                \
    issue(0, 0);                                                            \
    issue(32, 1);                                                           \
    {                                                                       \
        int s = 0;                                                          \
        for (int kt = 0; kt < (KEND); kt += 32) {                           \
            CP_WAIT1();                                                     \
            __syncthreads();                                                \
            issue(kt + 64, (s + 2) % NSTG);                                 \
            if (ACTIVE)                                                     \
                mma_tile1<TRANSB_>(acc, aS[s], bS[s], wm, wn, lane);        \
            s = (s + 1) % NSTG;                                             \
        }                                                                   \
    }

// ---------------------------------------------------------------------------
// Merged QKV projection (fp16 NN): grid (24, 64). bx>>3 selects W/output.
// ---------------------------------------------------------------------------
__global__ __launch_bounds__(256)
void gemm_qkv(const __half* __restrict__ Xh, const __half* __restrict__ Wh,
              __half* __restrict__ Qh, __half* __restrict__ Kh,
              __half* __restrict__ Vh)
{
    constexpr int ASZ = 128 * ASTR;
    constexpr int BSZ = 32 * BSTR;
    constexpr int STG = ASZ + BSZ;
    extern __shared__ __half smemh[];

    const int wsel = blockIdx.x >> 3;
    const int n0 = (blockIdx.x & 7) * 128;
    const int m0 = blockIdx.y * 128;

    const __half* Bh = Wh + (long)wsel * HID * DIM;
    __half* Out = (wsel == 0) ? Qh : (wsel == 1) ? Kh : Vh;

    const int tid  = threadIdx.x;
    const int lane = tid & 31;
    const int wm   = ((tid >> 5) & 3) * 32;
    const int wn   = (tid >> 7) * 64;

    uint32_t aS[NSTG], bS[NSTG];
    #pragma unroll
    for (int s = 0; s < NSTG; ++s) {
        uint32_t base = smem_u32(smemh + s * STG);
        aS[s] = base;
        bS[s] = base + ASZ * 2;
    }

    auto issue = [&](int kt, int s) {
        if (kt < HID) {
            #pragma unroll
            for (int i = 0; i < 2; ++i) {
                int q = tid + i * 256;
                int r = q >> 2, c = (q & 3) * 8;
                uint32_t doff = (uint32_t)(r * ASTR + c) * 2;
                cpa16(aS[s] + doff, Xh + (long)(m0 + r) * HID + kt + c);
                int kk = q >> 4, nn = (q & 15) * 8;
                uint32_t boff = (uint32_t)(kk * BSTR + nn) * 2;
                cpa16(bS[s] + boff, Bh + (long)(kt + kk) * DIM + n0 + nn);
            }
        }
        CP_COMMIT();
    };

    ACC_DECL();
    GEMM_MAINLOOP(HID, true, false);

    #pragma unroll
    for (int mt = 0; mt < 2; ++mt) {
        #pragma unroll
        for (int nt = 0; nt < 8; ++nt) {
            int row = m0 + wm + mt * 16 + (lane >> 2);
            int col = n0 + wn + nt * 8 + (lane & 3) * 2;
            float* f = acc[mt][nt];
            *(__half2*)(Out + (long)row * DIM + col) =
                __floats2half2_rn(f[0], f[1]);
            *(__half2*)(Out + (long)(row + 8) * DIM + col) =
                __floats2half2_rn(f[2], f[3]);
        }
    }
}

// ---------------------------------------------------------------------------
// Scores GEMM (NT fp16, causal): P = SCALE * Q @ K^T, fp32 out.
// ---------------------------------------------------------------------------
__global__ __launch_bounds__(256)
void gemm_scores(const __half* __restrict__ Qh, const __half* __restrict__ Kh,
                 float* __restrict__ P)
{
    constexpr int ASZ = 128 * ASTR;
    constexpr int STG = 2 * ASZ;
    extern __shared__ __half smemh[];

    const int m0 = blockIdx.y * 128;
    const int n0 = blockIdx.x * 128;
    if (n0 > m0 + 127) return;

    const long zoff = (long)blockIdx.z * SEQ * DIM;
    Qh += zoff; Kh += zoff;
    P += (long)blockIdx.z * SEQ * SEQ;

    const int tid  = threadIdx.x;
    const int lane = tid & 31;
    const int wm   = ((tid >> 5) & 3) * 32;
    const int wn   = (tid >> 7) * 64;
    const bool active = (n0 + wn) <= (m0 + wm + 31);

    uint32_t aS[NSTG], bS[NSTG];
    #pragma unroll
    for (int s = 0; s < NSTG; ++s) {
        uint32_t base = smem_u32(smemh + s * STG);
        aS[s] = base;
        bS[s] = base + ASZ * 2;
    }

    auto issue = [&](int kt, int s) {
        if (kt < DIM) {
            #pragma unroll
            for (int i = 0; i < 2; ++i) {
                int q = tid + i * 256;
                int r = q >> 2, c = (q & 3) * 8;
                uint32_t doff = (uint32_t)(r * ASTR + c) * 2;
                cpa16(aS[s] + doff, Qh + (long)(m0 + r) * DIM + kt + c);
                cpa16(bS[s] + doff, Kh + (long)(n0 + r) * DIM + kt + c);
            }
        }
        CP_COMMIT();
    };

    ACC_DECL();
    GEMM_MAINLOOP(DIM, active, true);

    if (active) {
        #pragma unroll
        for (int mt = 0; mt < 2; ++mt) {
            #pragma unroll
            for (int nt = 0; nt < 8; ++nt) {
                int row = m0 + wm + mt * 16 + (lane >> 2);
                int col = n0 + wn + nt * 8 + (lane & 3) * 2;
                float* f = acc[mt][nt];
                *(float2*)(P + (long)row * SEQ + col) =
                    make_float2(SCALE * f[0], SCALE * f[1]);
                *(float2*)(P + (long)(row + 8) * SEQ + col) =
                    make_float2(SCALE * f[2], SCALE * f[3]);
            }
        }
    }
}

// ---------------------------------------------------------------------------
// PV GEMM (NN fp16, K bounded): out = P @ V, fp32 out.
// ---------------------------------------------------------------------------
__global__ __launch_bounds__(256)
void gemm_pv(const __half* __restrict__ Ph, const __half* __restrict__ Vh,
             float* __restrict__ Out)
{
    constexpr int ASZ = 128 * ASTR;
    constexpr int BSZ = 32 * BSTR;
    constexpr int STG = ASZ + BSZ;
    extern __shared__ __half smemh[];

    const int m0 = blockIdx.y * 128;
    const int n0 = blockIdx.x * 128;

    Ph += (long)blockIdx.z * SEQ * SEQ;
    Vh += (long)blockIdx.z * SEQ * DIM;
    Out += (long)blockIdx.z * SEQ * DIM;

    const int tid  = threadIdx.x;
    const int lane = tid & 31;
    const int wm   = ((tid >> 5) & 3) * 32;
    const int wn   = (tid >> 7) * 64;
    const int kEnd = m0 + 128;   // P zero beyond diagonal tile edge

    uint32_t aS[NSTG], bS[NSTG];
    #pragma unroll
    for (int s = 0; s < NSTG; ++s) {
        uint32_t base = smem_u32(smemh + s * STG);
        aS[s] = base;
        bS[s] = base + ASZ * 2;
    }

    auto issue = [&](int kt, int s) {
        if (kt < kEnd) {
            #pragma unroll
            for (int i = 0; i < 2; ++i) {
                int q = tid + i * 256;
                int r = q >> 2, c = (q & 3) * 8;
                uint32_t doff = (uint32_t)(r * ASTR + c) * 2;
                cpa16(aS[s] + doff, Ph + (long)(m0 + r) * SEQ + kt + c);
                int kk = q >> 4, nn = (q & 15) * 8;
                uint32_t boff = (uint32_t)(kk * BSTR + nn) * 2;
                cpa16(bS[s] + boff, Vh + (long)(kt + kk) * DIM + n0 + nn);
            }
        }
        CP_COMMIT();
    };

    ACC_DECL();
    GEMM_MAINLOOP(kEnd, true, false);

    #pragma unroll
    for (int mt = 0; mt < 2; ++mt) {
        #pragma unroll
        for (int nt = 0; nt < 8; ++nt) {
            int row = m0 + wm + mt * 16 + (lane >> 2);
            int col = n0 + wn + nt * 8 + (lane & 3) * 2;
            float* f = acc[mt][nt];
            *(float2*)(Out + (long)row * DIM + col) = make_float2(f[0], f[1]);
            *(float2*)(Out + (long)(row + 8) * DIM + col) = make_float2(f[2], f[3]);
        }
    }
}

// ---------------------------------------------------------------------------
// Causal softmax: fp32 scores -> fp16 normalized probabilities.
// Writes only j < (i & ~127) + 128 — PV never reads beyond the tile edge.
// ---------------------------------------------------------------------------
__global__ __launch_bounds__(256)
void softmax_causal(const float* __restrict__ P, __half* __restrict__ Ph)
{
    const int S = SEQ;
    const int i = blockIdx.x, b = blockIdx.y;
    const float* row = P + ((long)b * S + i) * S;
    __half* hrow = Ph + ((long)b * S + i) * S;

    __shared__ float buf[SEQ];
    __shared__ float red[256];
    const int tid = threadIdx.x;
    const int L = i + 1;
    const int kBound = (i & ~127) + 128;   // PV read bound for this row

    float m = -3.0e38f;
    for (int j = tid; j < L; j += 256) {
        float v = row[j];
        buf[j] = v;
        m = fmaxf(m, v);
    }
    red[tid] = m;
    __syncthreads();
    #pragma unroll
    for (int sd = 128; sd > 0; sd >>= 1) {
        if (tid < sd) red[tid] = fmaxf(red[tid], red[tid + sd]);
        __syncthreads();
    }
    m = red[0];
    __syncthreads();

    float sum = 0.f;
    for (int j = tid; j < L; j += 256) {
        float e = expf(buf[j] - m);
        buf[j] = e;
        sum += e;
    }
    red[tid] = sum;
    __syncthreads();
    #pragma unroll
    for (int sd = 128; sd > 0; sd >>= 1) {
        if (tid < sd) red[tid] += red[tid + sd];
        __syncthreads();
    }
    const float inv = 1.0f / red[0];

    for (int j = tid; j < kBound; j += 256) {
        float v = (j < L) ? buf[j] * inv : 0.f;
        hrow[j] = __float2half_rn(v);
    }
}

// ---------------------------------------------------------------------------
extern "C" void kernel_launch(void* const* d_in, const int* in_sizes, int n_in,
                              void* d_out, int out_size)
{
    (void)in_sizes; (void)n_in; (void)out_size;
    const float* X  = (const float*)d_in[0];
    const float* Wq = (const float*)d_in[1];
    const float* Wk = (const float*)d_in[2];
    const float* Wv = (const float*)d_in[3];
    float* out = (float*)d_out;

    #define SYM(v, s) void* v; cudaGetSymbolAddress(&v, s)
    SYM(pP, g_P); SYM(pXh, g_Xh); SYM(pWh, g_Wh);
    SYM(pQh, g_Qh); SYM(pKh, g_Kh); SYM(pVh, g_Vh); SYM(pPh, g_Ph);
    #undef SYM

    const int NN_SMEM = NSTG * (128 * ASTR + 32 * BSTR) * 2;   // 56832 B
    const int NT_SMEM = NSTG * (2 * 128 * ASTR) * 2;           // 61440 B

    cudaFuncSetAttribute(gemm_qkv, cudaFuncAttributeMaxDynamicSharedMemorySize,
                         NN_SMEM);
    cudaFuncSetAttribute(gemm_scores, cudaFuncAttributeMaxDynamicSharedMemorySize,
                         NT_SMEM);
    cudaFuncSetAttribute(gemm_pv, cudaFuncAttributeMaxDynamicSharedMemorySize,
                         NN_SMEM);

    // 0) fused fp16 quantization of X, Wq, Wk, Wv
    {
        long nX4 = (long)BATCH * SEQ * HID / 4;
        long nW4 = (long)HID * DIM / 4;
        quant_all<<<2960, 256>>>(X, Wq, Wk, Wv, (__half*)pXh, (__half*)pWh,
                                 nX4, nW4);
    }

    // 1) merged QKV projections (fp16) -> fp16 Q, K, V
    {
        dim3 grid(24, (BATCH * SEQ) / 128, 1);
        gemm_qkv<<<grid, 256, NN_SMEM>>>(
            (__half*)pXh, (__half*)pWh,
            (__half*)pQh, (__half*)pKh, (__half*)pVh);
    }

    // 2) scores = SCALE * Q @ K^T (fp16), causal blocks only
    {
        dim3 grid(SEQ / 128, SEQ / 128, BATCH);
        gemm_scores<<<grid, 256, NT_SMEM>>>(
            (__half*)pQh, (__half*)pKh, (float*)pP);
    }

    // 3) causal softmax -> fp16 normalized probabilities (bounded writes)
    {
        dim3 grid(SEQ, BATCH);
        softmax_causal<<<grid, 256>>>((float*)pP, (__half*)pPh);
    }

    // 4) out = P @ V (fp16), K bounded by causality
    {
        dim3 grid(DIM / 128, SEQ / 128, BATCH);
        gemm_pv<<<grid, 256, NN_SMEM>>>(
            (__half*)pPh, (__half*)pVh, out);
    }
}

// round 14
// speedup vs baseline: 1.0273x; 1.0273x over previous
#include <cuda_runtime.h>
#include <cuda_fp16.h>
#include <cstdint>
#include <math.h>

#define BATCH 4
#define SEQ   2048
#define HID   1024
#define DIM   1024
#define SCALE 0.03125f   // 1/sqrt(1024)

// Scratch (device globals; runtime allocation is forbidden)
__device__ float  g_P [(long)BATCH * SEQ * SEQ];
__device__ __half g_Xh[(long)BATCH * SEQ * HID];
__device__ __half g_Wh[(long)3 * HID * DIM];     // Wq,Wk,Wv stacked, [H][D] each
__device__ __half g_Qh[(long)BATCH * SEQ * DIM];
__device__ __half g_Kh[(long)BATCH * SEQ * DIM];
__device__ __half g_Vh[(long)BATCH * SEQ * DIM];
__device__ __half g_Ph[(long)BATCH * SEQ * SEQ];

// ---------------------------------------------------------------------------
// PTX helpers (baseline sm_80-level PTX)
// ---------------------------------------------------------------------------
__device__ __forceinline__ uint32_t smem_u32(const void* p) {
    uint32_t a;
    asm("{ .reg .u64 t; cvta.to.shared.u64 t, %1; cvt.u32.u64 %0, t; }"
        : "=r"(a) : "l"(p));
    return a;
}
__device__ __forceinline__ void cpa16(uint32_t dst, const void* src) {
    asm volatile("cp.async.cg.shared.global [%0], [%1], 16;" :: "r"(dst), "l"(src));
}
#define CP_COMMIT() asm volatile("cp.async.commit_group;" ::: "memory")
#define CP_WAIT1()  asm volatile("cp.async.wait_group 1;" ::: "memory")

__device__ __forceinline__ void ldsm_x4(uint32_t* r, uint32_t addr) {
    asm volatile("ldmatrix.sync.aligned.m8n8.x4.shared.b16 {%0,%1,%2,%3}, [%4];"
                 : "=r"(r[0]), "=r"(r[1]), "=r"(r[2]), "=r"(r[3]) : "r"(addr));
}
__device__ __forceinline__ void ldsm_x4_t(uint32_t* r, uint32_t addr) {
    asm volatile("ldmatrix.sync.aligned.m8n8.x4.trans.shared.b16 {%0,%1,%2,%3}, [%4];"
                 : "=r"(r[0]), "=r"(r[1]), "=r"(r[2]), "=r"(r[3]) : "r"(addr));
}
__device__ __forceinline__ void mma_f16(float* c, const uint32_t* a,
                                        const uint32_t* b) {
    asm volatile(
        "mma.sync.aligned.m16n8k16.row.col.f32.f16.f16.f32 "
        "{%0,%1,%2,%3}, {%4,%5,%6,%7}, {%8,%9}, {%0,%1,%2,%3};"
        : "+f"(c[0]), "+f"(c[1]), "+f"(c[2]), "+f"(c[3])
        : "r"(a[0]), "r"(a[1]), "r"(a[2]), "r"(a[3]), "r"(b[0]), "r"(b[1]));
}

// ---------------------------------------------------------------------------
// Fused fp32 -> fp16 quantize for X, Wq, Wk, Wv in one launch.
// ---------------------------------------------------------------------------
__global__ __launch_bounds__(256)
void quant_all(const float* __restrict__ X, const float* __restrict__ Wq,
               const float* __restrict__ Wk, const float* __restrict__ Wv,
               __half* __restrict__ Xh, __half* __restrict__ Wh,
               long nX4, long nW4)
{
    long total = nX4 + 3 * nW4;
    long i = blockIdx.x * 256 + threadIdx.x;
    long stride = (long)gridDim.x * 256;
    for (; i < total; i += stride) {
        const float* src;
        __half* dst;
        long j;
        if (i < nX4) {
            src = X; dst = Xh; j = i;
        } else {
            long k = i - nX4;
            int w = (int)(k / nW4);
            j = k - (long)w * nW4;
            src = (w == 0) ? Wq : (w == 1) ? Wk : Wv;
            dst = Wh + (long)w * HID * DIM;
        }
        float4 v = *(const float4*)(src + j * 4);
        __half2 h0 = __floats2half2_rn(v.x, v.y);
        __half2 h1 = __floats2half2_rn(v.z, v.w);
        uint2 u;
        u.x = reinterpret_cast<uint32_t&>(h0);
        u.y = reinterpret_cast<uint32_t&>(h1);
        *(uint2*)(dst + j * 4) = u;
    }
}

// ---------------------------------------------------------------------------
// Tiling config: BM=BN=128, BK=32, 256 threads, 8 warps (4m x 2n),
// warp tile 32x64. 3-stage cp.async pipeline, one barrier per k-iter.
// ---------------------------------------------------------------------------
#define ASTR 40
#define BSTR 136
#define NSTG 3

template <bool TRANSB>
__device__ __forceinline__ void mma_tile1(
    float acc[2][8][4], uint32_t aS, uint32_t bS, int wm, int wn, int lane)
{
    #pragma unroll
    for (int ks = 0; ks < 2; ++ks) {
        uint32_t aF[2][4];
        #pragma unroll
        for (int mt = 0; mt < 2; ++mt) {
            uint32_t off =
                ((uint32_t)(wm + mt * 16 + (lane & 15)) * ASTR +
                 ks * 16 + (lane >> 4) * 8) * 2;
            ldsm_x4(aF[mt], aS + off);
        }
        #pragma unroll
        for (int np = 0; np < 4; ++np) {
            uint32_t bF[4];
            if (TRANSB) {
                uint32_t nrow = wn + np * 16 + (lane & 7) + (lane >> 4) * 8;
                uint32_t off = (nrow * ASTR + ks * 16 + ((lane >> 3) & 1) * 8) * 2;
                ldsm_x4(bF, bS + off);
            } else {
                uint32_t krow = ks * 16 + (lane & 15);
                uint32_t ncol = wn + np * 16 + (lane >> 4) * 8;
                uint32_t off = (krow * BSTR + ncol) * 2;
                ldsm_x4_t(bF, bS + off);
            }
            #pragma unroll
            for (int h = 0; h < 2; ++h) {
                #pragma unroll
                for (int mt = 0; mt < 2; ++mt)
                    mma_f16(acc[mt][np * 2 + h], aF[mt], bF + h * 2);
            }
        }
    }
}

#define ACC_DECL()                                                          \
    float acc[2][8][4];                                                     \
    _Pragma("unroll")                                                       \
    for (int i_ = 0; i_ < 2; ++i_)                                          \
        _Pragma("unroll")                                                   \
        for (int j_ = 0; j_ < 8; ++j_)                                      \
            _Pragma("unroll")                                               \
            for (int t_ = 0; t_ < 4; ++t_) acc[i_][j_][t_] = 0.f;

#define GEMM_MAINLOOP(KEND, ACTIVE, TRANSB_)                                \
    issue(0, 0);                                                            \
    issue(32, 1);                                                           \
    {                                                                       \
        int s = 0;                                                          \
        for (int kt = 0; kt < (KEND); kt += 32) {                           \
            CP_WAIT1();                                                     \
            __syncthreads();                                                \
            issue(kt + 64, (s + 2) % NSTG);                                 \
            if (ACTIVE)                                                     \
                mma_tile1<TRANSB_>(acc, aS[s], bS[s], wm, wn, lane);        \
            s = (s + 1) % NSTG;                                             \
        }                                                                   \
    }

// ---------------------------------------------------------------------------
// Merged QKV projection (fp16 NN): grid (24, 64). bx>>3 selects W/output.
// ---------------------------------------------------------------------------
__global__ __launch_bounds__(256)
void gemm_qkv(const __half* __restrict__ Xh, const __half* __restrict__ Wh,
              __half* __restrict__ Qh, __half* __restrict__ Kh,
              __half* __restrict__ Vh)
{
    constexpr int ASZ = 128 * ASTR;
    constexpr int BSZ = 32 * BSTR;
    constexpr int STG = ASZ + BSZ;
    extern __shared__ __half smemh[];

    const int wsel = blockIdx.x >> 3;
    const int n0 = (blockIdx.x & 7) * 128;
    const int m0 = blockIdx.y * 128;

    const __half* Bh = Wh + (long)wsel * HID * DIM;
    __half* Out = (wsel == 0) ? Qh : (wsel == 1) ? Kh : Vh;

    const int tid  = threadIdx.x;
    const int lane = tid & 31;
    const int wm   = ((tid >> 5) & 3) * 32;
    const int wn   = (tid >> 7) * 64;

    uint32_t aS[NSTG], bS[NSTG];
    #pragma unroll
    for (int s = 0; s < NSTG; ++s) {
        uint32_t base = smem_u32(smemh + s * STG);
        aS[s] = base;
        bS[s] = base + ASZ * 2;
    }

    auto issue = [&](int kt, int s) {
        if (kt < HID) {
            #pragma unroll
            for (int i = 0; i < 2; ++i) {
                int q = tid + i * 256;
                int r = q >> 2, c = (q & 3) * 8;
                uint32_t doff = (uint32_t)(r * ASTR + c) * 2;
                cpa16(aS[s] + doff, Xh + (long)(m0 + r) * HID + kt + c);
                int kk = q >> 4, nn = (q & 15) * 8;
                uint32_t boff = (uint32_t)(kk * BSTR + nn) * 2;
                cpa16(bS[s] + boff, Bh + (long)(kt + kk) * DIM + n0 + nn);
            }
        }
        CP_COMMIT();
    };

    ACC_DECL();
    GEMM_MAINLOOP(HID, true, false);

    #pragma unroll
    for (int mt = 0; mt < 2; ++mt) {
        #pragma unroll
        for (int nt = 0; nt < 8; ++nt) {
            int row = m0 + wm + mt * 16 + (lane >> 2);
            int col = n0 + wn + nt * 8 + (lane & 3) * 2;
            float* f = acc[mt][nt];
            *(__half2*)(Out + (long)row * DIM + col) =
                __floats2half2_rn(f[0], f[1]);
            *(__half2*)(Out + (long)(row + 8) * DIM + col) =
                __floats2half2_rn(f[2], f[3]);
        }
    }
}

// ---------------------------------------------------------------------------
// Scores GEMM (NT fp16, causal): P = Q @ K^T raw dot (SCALE folded into
// softmax), fp32 out.
// ---------------------------------------------------------------------------
__global__ __launch_bounds__(256)
void gemm_scores(const __half* __restrict__ Qh, const __half* __restrict__ Kh,
                 float* __restrict__ P)
{
    constexpr int ASZ = 128 * ASTR;
    constexpr int STG = 2 * ASZ;
    extern __shared__ __half smemh[];

    const int m0 = blockIdx.y * 128;
    const int n0 = blockIdx.x * 128;
    if (n0 > m0 + 127) return;

    const long zoff = (long)blockIdx.z * SEQ * DIM;
    Qh += zoff; Kh += zoff;
    P += (long)blockIdx.z * SEQ * SEQ;

    const int tid  = threadIdx.x;
    const int lane = tid & 31;
    const int wm   = ((tid >> 5) & 3) * 32;
    const int wn   = (tid >> 7) * 64;
    const bool active = (n0 + wn) <= (m0 + wm + 31);

    uint32_t aS[NSTG], bS[NSTG];
    #pragma unroll
    for (int s = 0; s < NSTG; ++s) {
        uint32_t base = smem_u32(smemh + s * STG);
        aS[s] = base;
        bS[s] = base + ASZ * 2;
    }

    auto issue = [&](int kt, int s) {
        if (kt < DIM) {
            #pragma unroll
            for (int i = 0; i < 2; ++i) {
                int q = tid + i * 256;
                int r = q >> 2, c = (q & 3) * 8;
                uint32_t doff = (uint32_t)(r * ASTR + c) * 2;
                cpa16(aS[s] + doff, Qh + (long)(m0 + r) * DIM + kt + c);
                cpa16(bS[s] + doff, Kh + (long)(n0 + r) * DIM + kt + c);
            }
        }
        CP_COMMIT();
    };

    ACC_DECL();
    GEMM_MAINLOOP(DIM, active, true);

    if (active) {
        #pragma unroll
        for (int mt = 0; mt < 2; ++mt) {
            #pragma unroll
            for (int nt = 0; nt < 8; ++nt) {
                int row = m0 + wm + mt * 16 + (lane >> 2);
                int col = n0 + wn + nt * 8 + (lane & 3) * 2;
                float* f = acc[mt][nt];
                *(float2*)(P + (long)row * SEQ + col) = make_float2(f[0], f[1]);
                *(float2*)(P + (long)(row + 8) * SEQ + col) =
                    make_float2(f[2], f[3]);
            }
        }
    }
}

// ---------------------------------------------------------------------------
// PV GEMM (NN fp16, K bounded): out = P @ V, fp32 out.
// Longest-K tiles scheduled first (m0 reversed) for wave balance.
// ---------------------------------------------------------------------------
__global__ __launch_bounds__(256)
void gemm_pv(const __half* __restrict__ Ph, const __half* __restrict__ Vh,
             float* __restrict__ Out)
{
    constexpr int ASZ = 128 * ASTR;
    constexpr int BSZ = 32 * BSTR;
    constexpr int STG = ASZ + BSZ;
    extern __shared__ __half smemh[];

    const int m0 = (int)(gridDim.y - 1 - blockIdx.y) * 128;  // longest first
    const int n0 = blockIdx.x * 128;

    Ph += (long)blockIdx.z * SEQ * SEQ;
    Vh += (long)blockIdx.z * SEQ * DIM;
    Out += (long)blockIdx.z * SEQ * DIM;

    const int tid  = threadIdx.x;
    const int lane = tid & 31;
    const int wm   = ((tid >> 5) & 3) * 32;
    const int wn   = (tid >> 7) * 64;
    const int kEnd = m0 + 128;   // P zero beyond diagonal tile edge

    uint32_t aS[NSTG], bS[NSTG];
    #pragma unroll
    for (int s = 0; s < NSTG; ++s) {
        uint32_t base = smem_u32(smemh + s * STG);
        aS[s] = base;
        bS[s] = base + ASZ * 2;
    }

    auto issue = [&](int kt, int s) {
        if (kt < kEnd) {
            #pragma unroll
            for (int i = 0; i < 2; ++i) {
                int q = tid + i * 256;
                int r = q >> 2, c = (q & 3) * 8;
                uint32_t doff = (uint32_t)(r * ASTR + c) * 2;
                cpa16(aS[s] + doff, Ph + (long)(m0 + r) * SEQ + kt + c);
                int kk = q >> 4, nn = (q & 15) * 8;
                uint32_t boff = (uint32_t)(kk * BSTR + nn) * 2;
                cpa16(bS[s] + boff, Vh + (long)(kt + kk) * DIM + n0 + nn);
            }
        }
        CP_COMMIT();
    };

    ACC_DECL();
    GEMM_MAINLOOP(kEnd, true, false);

    #pragma unroll
    for (int mt = 0; mt < 2; ++mt) {
        #pragma unroll
        for (int nt = 0; nt < 8; ++nt) {
            int row = m0 + wm + mt * 16 + (lane >> 2);
            int col = n0 + wn + nt * 8 + (lane & 3) * 2;
            float* f = acc[mt][nt];
            *(float2*)(Out + (long)row * DIM + col) = make_float2(f[0], f[1]);
            *(float2*)(Out + (long)(row + 8) * DIM + col) = make_float2(f[2], f[3]);
        }
    }
}

// ---------------------------------------------------------------------------
// Causal softmax (vectorized): raw scores -> fp16 normalized probabilities.
// SCALE applied here. float4 loads, __expf, half2 stores.
// Writes only j < (i & ~127) + 128 (PV read bound; multiple of 128).
// ---------------------------------------------------------------------------
__global__ __launch_bounds__(256)
void softmax_causal(const float* __restrict__ P, __half* __restrict__ Ph)
{
    const int S = SEQ;
    const int i = blockIdx.x, b = blockIdx.y;
    const float* row = P + ((long)b * S + i) * S;
    __half* hrow = Ph + ((long)b * S + i) * S;

    __shared__ float buf[SEQ];
    __shared__ float red[256];
    const int tid = threadIdx.x;
    const int L = i + 1;
    const int kB4 = ((i & ~127) + 128) >> 2;   // bound in float4 units

    // pass 1: scaled load + max (mask j >= L)
    float m = -3.0e38f;
    for (int j4 = tid; j4 < kB4; j4 += 256) {
        float4 v = *(const float4*)(row + j4 * 4);
        int j = j4 * 4;
        v.x = (j + 0 < L) ? v.x * SCALE : -3.0e38f;
        v.y = (j + 1 < L) ? v.y * SCALE : -3.0e38f;
        v.z = (j + 2 < L) ? v.z * SCALE : -3.0e38f;
        v.w = (j + 3 < L) ? v.w * SCALE : -3.0e38f;
        *(float4*)(buf + j) = v;
        m = fmaxf(m, fmaxf(fmaxf(v.x, v.y), fmaxf(v.z, v.w)));
    }
    red[tid] = m;
    __syncthreads();
    #pragma unroll
    for (int sd = 128; sd > 0; sd >>= 1) {
        if (tid < sd) red[tid] = fmaxf(red[tid], red[tid + sd]);
        __syncthreads();
    }
    m = red[0];
    __syncthreads();

    // pass 2: exp + sum (masked lanes hold -3e38 -> exp ~ 0)
    float sum = 0.f;
    for (int j4 = tid; j4 < kB4; j4 += 256) {
        float4 v = *(const float4*)(buf + j4 * 4);
        v.x = __expf(v.x - m);
        v.y = __expf(v.y - m);
        v.z = __expf(v.z - m);
        v.w = __expf(v.w - m);
        *(float4*)(buf + j4 * 4) = v;
        sum += v.x + v.y + v.z + v.w;
    }
    red[tid] = sum;
    __syncthreads();
    #pragma unroll
    for (int sd = 128; sd > 0; sd >>= 1) {
        if (tid < sd) red[tid] += red[tid + sd];
        __syncthreads();
    }
    const float inv = 1.0f / red[0];

    // pass 3: normalize + half2 stores
    for (int j4 = tid; j4 < kB4; j4 += 256) {
        float4 v = *(const float4*)(buf + j4 * 4);
        __half2 h0 = __floats2half2_rn(v.x * inv, v.y * inv);
        __half2 h1 = __floats2half2_rn(v.z * inv, v.w * inv);
        uint2 u;
        u.x = reinterpret_cast<uint32_t&>(h0);
        u.y = reinterpret_cast<uint32_t&>(h1);
        *(uint2*)(hrow + j4 * 4) = u;
    }
}

// ---------------------------------------------------------------------------
extern "C" void kernel_launch(void* const* d_in, const int* in_sizes, int n_in,
                              void* d_out, int out_size)
{
    (void)in_sizes; (void)n_in; (void)out_size;
    const float* X  = (const float*)d_in[0];
    const float* Wq = (const float*)d_in[1];
    const float* Wk = (const float*)d_in[2];
    const float* Wv = (const float*)d_in[3];
    float* out = (float*)d_out;

    #define SYM(v, s) void* v; cudaGetSymbolAddress(&v, s)
    SYM(pP, g_P); SYM(pXh, g_Xh); SYM(pWh, g_Wh);
    SYM(pQh, g_Qh); SYM(pKh, g_Kh); SYM(pVh, g_Vh); SYM(pPh, g_Ph);
    #undef SYM

    const int NN_SMEM = NSTG * (128 * ASTR + 32 * BSTR) * 2;   // 56832 B
    const int NT_SMEM = NSTG * (2 * 128 * ASTR) * 2;           // 61440 B

    cudaFuncSetAttribute(gemm_qkv, cudaFuncAttributeMaxDynamicSharedMemorySize,
                         NN_SMEM);
    cudaFuncSetAttribute(gemm_scores, cudaFuncAttributeMaxDynamicSharedMemorySize,
                         NT_SMEM);
    cudaFuncSetAttribute(gemm_pv, cudaFuncAttributeMaxDynamicSharedMemorySize,
                         NN_SMEM);

    // 0) fused fp16 quantization of X, Wq, Wk, Wv
    {
        long nX4 = (long)BATCH * SEQ * HID / 4;
        long nW4 = (long)HID * DIM / 4;
        quant_all<<<2960, 256>>>(X, Wq, Wk, Wv, (__half*)pXh, (__half*)pWh,
                                 nX4, nW4);
    }

    // 1) merged QKV projections (fp16) -> fp16 Q, K, V
    {
        dim3 grid(24, (BATCH * SEQ) / 128, 1);
        gemm_qkv<<<grid, 256, NN_SMEM>>>(
            (__half*)pXh, (__half*)pWh,
            (__half*)pQh, (__half*)pKh, (__half*)pVh);
    }

    // 2) raw scores = Q @ K^T (fp16), causal blocks only
    {
        dim3 grid(SEQ / 128, SEQ / 128, BATCH);
        gemm_scores<<<grid, 256, NT_SMEM>>>(
            (__half*)pQh, (__half*)pKh, (float*)pP);
    }

    // 3) causal softmax (SCALE folded in) -> fp16 probabilities
    {
        dim3 grid(SEQ, BATCH);
        softmax_causal<<<grid, 256>>>((float*)pP, (__half*)pPh);
    }

    // 4) out = P @ V (fp16), K bounded by causality, longest tiles first
    {
        dim3 grid(DIM / 128, SEQ / 128, BATCH);
        gemm_pv<<<grid, 256, NN_SMEM>>>(
            (__half*)pPh, (__half*)pVh, out);
    }
}

// round 15
// speedup vs baseline: 1.0462x; 1.0184x over previous
#include <cuda_runtime.h>
#include <cuda_fp16.h>
#include <cstdint>
#include <math.h>

#define BATCH 4
#define SEQ   2048
#define HID   1024
#define DIM   1024
#define SCALE 0.03125f   // 1/sqrt(1024)

// Scratch (device globals; runtime allocation is forbidden)
__device__ float  g_P [(long)BATCH * SEQ * SEQ];
__device__ float  g_rs[(long)BATCH * SEQ];       // per-row 1/sum
__device__ __half g_Xh[(long)BATCH * SEQ * HID];
__device__ __half g_Wh[(long)3 * HID * DIM];     // Wq,Wk,Wv stacked, [H][D] each
__device__ __half g_Qh[(long)BATCH * SEQ * DIM];
__device__ __half g_Kh[(long)BATCH * SEQ * DIM];
__device__ __half g_Vh[(long)BATCH * SEQ * DIM];
__device__ __half g_Ph[(long)BATCH * SEQ * SEQ];

// ---------------------------------------------------------------------------
// PTX helpers (baseline sm_80-level PTX)
// ---------------------------------------------------------------------------
__device__ __forceinline__ uint32_t smem_u32(const void* p) {
    uint32_t a;
    asm("{ .reg .u64 t; cvta.to.shared.u64 t, %1; cvt.u32.u64 %0, t; }"
        : "=r"(a) : "l"(p));
    return a;
}
__device__ __forceinline__ void cpa16(uint32_t dst, const void* src) {
    asm volatile("cp.async.cg.shared.global [%0], [%1], 16;" :: "r"(dst), "l"(src));
}
#define CP_COMMIT() asm volatile("cp.async.commit_group;" ::: "memory")
#define CP_WAIT1()  asm volatile("cp.async.wait_group 1;" ::: "memory")

__device__ __forceinline__ void ldsm_x4(uint32_t* r, uint32_t addr) {
    asm volatile("ldmatrix.sync.aligned.m8n8.x4.shared.b16 {%0,%1,%2,%3}, [%4];"
                 : "=r"(r[0]), "=r"(r[1]), "=r"(r[2]), "=r"(r[3]) : "r"(addr));
}
__device__ __forceinline__ void ldsm_x4_t(uint32_t* r, uint32_t addr) {
    asm volatile("ldmatrix.sync.aligned.m8n8.x4.trans.shared.b16 {%0,%1,%2,%3}, [%4];"
                 : "=r"(r[0]), "=r"(r[1]), "=r"(r[2]), "=r"(r[3]) : "r"(addr));
}
__device__ __forceinline__ void mma_f16(float* c, const uint32_t* a,
                                        const uint32_t* b) {
    asm volatile(
        "mma.sync.aligned.m16n8k16.row.col.f32.f16.f16.f32 "
        "{%0,%1,%2,%3}, {%4,%5,%6,%7}, {%8,%9}, {%0,%1,%2,%3};"
        : "+f"(c[0]), "+f"(c[1]), "+f"(c[2]), "+f"(c[3])
        : "r"(a[0]), "r"(a[1]), "r"(a[2]), "r"(a[3]), "r"(b[0]), "r"(b[1]));
}

// ---------------------------------------------------------------------------
// Fused fp32 -> fp16 quantize for X, Wq, Wk, Wv in one launch.
// ---------------------------------------------------------------------------
__global__ __launch_bounds__(256)
void quant_all(const float* __restrict__ X, const float* __restrict__ Wq,
               const float* __restrict__ Wk, const float* __restrict__ Wv,
               __half* __restrict__ Xh, __half* __restrict__ Wh,
               long nX4, long nW4)
{
    long total = nX4 + 3 * nW4;
    long i = blockIdx.x * 256 + threadIdx.x;
    long stride = (long)gridDim.x * 256;
    for (; i < total; i += stride) {
        const float* src;
        __half* dst;
        long j;
        if (i < nX4) {
            src = X; dst = Xh; j = i;
        } else {
            long k = i - nX4;
            int w = (int)(k / nW4);
            j = k - (long)w * nW4;
            src = (w == 0) ? Wq : (w == 1) ? Wk : Wv;
            dst = Wh + (long)w * HID * DIM;
        }
        float4 v = *(const float4*)(src + j * 4);
        __half2 h0 = __floats2half2_rn(v.x, v.y);
        __half2 h1 = __floats2half2_rn(v.z, v.w);
        uint2 u;
        u.x = reinterpret_cast<uint32_t&>(h0);
        u.y = reinterpret_cast<uint32_t&>(h1);
        *(uint2*)(dst + j * 4) = u;
    }
}

// ---------------------------------------------------------------------------
// Tiling config: BM=BN=128, BK=32, 256 threads, 8 warps (4m x 2n),
// warp tile 32x64. 3-stage cp.async pipeline, one barrier per k-iter.
// ---------------------------------------------------------------------------
#define ASTR 40
#define BSTR 136
#define NSTG 3

template <bool TRANSB>
__device__ __forceinline__ void mma_tile1(
    float acc[2][8][4], uint32_t aS, uint32_t bS, int wm, int wn, int lane)
{
    #pragma unroll
    for (int ks = 0; ks < 2; ++ks) {
        uint32_t aF[2][4];
        #pragma unroll
        for (int mt = 0; mt < 2; ++mt) {
            uint32_t off =
                ((uint32_t)(wm + mt * 16 + (lane & 15)) * ASTR +
                 ks * 16 + (lane >> 4) * 8) * 2;
            ldsm_x4(aF[mt], aS + off);
        }
        #pragma unroll
        for (int np = 0; np < 4; ++np) {
            uint32_t bF[4];
            if (TRANSB) {
                uint32_t nrow = wn + np * 16 + (lane & 7) + (lane >> 4) * 8;
                uint32_t off = (nrow * ASTR + ks * 16 + ((lane >> 3) & 1) * 8) * 2;
                ldsm_x4(bF, bS + off);
            } else {
                uint32_t krow = ks * 16 + (lane & 15);
                uint32_t ncol = wn + np * 16 + (lane >> 4) * 8;
                uint32_t off = (krow * BSTR + ncol) * 2;
                ldsm_x4_t(bF, bS + off);
            }
            #pragma unroll
            for (int h = 0; h < 2; ++h) {
                #pragma unroll
                for (int mt = 0; mt < 2; ++mt)
                    mma_f16(acc[mt][np * 2 + h], aF[mt], bF + h * 2);
            }
        }
    }
}

#define ACC_DECL()                                                          \
    float acc[2][8][4];                                                     \
    _Pragma("unroll")                                                       \
    for (int i_ = 0; i_ < 2; ++i_)                                          \
        _Pragma("unroll")                                                   \
        for (int j_ = 0; j_ < 8; ++j_)                                      \
            _Pragma("unroll")                                               \
            for (int t_ = 0; t_ < 4; ++t_) acc[i_][j_][t_] = 0.f;

#define GEMM_MAINLOOP(KEND, ACTIVE, TRANSB_)                                \
    issue(0, 0);                                                            \
    issue(32, 1);                                                            \
    {                                                                       \
        int s = 0;                                                          \
        for (int kt = 0; kt < (KEND); kt += 32) {                           \
            CP_WAIT1();                                                     \
            __syncthreads();                                                \
            issue(kt + 64, (s + 2) % NSTG);                                 \
            if (ACTIVE)                                                     \
                mma_tile1<TRANSB_>(acc, aS[s], bS[s], wm, wn, lane);        \
            s = (s + 1) % NSTG;                                             \
        }                                                                   \
    }

// ---------------------------------------------------------------------------
// Merged QKV projection (fp16 NN): grid (24, 64). bx>>3 selects W/output.
// ---------------------------------------------------------------------------
__global__ __launch_bounds__(256)
void gemm_qkv(const __half* __restrict__ Xh, const __half* __restrict__ Wh,
              __half* __restrict__ Qh, __half* __restrict__ Kh,
              __half* __restrict__ Vh)
{
    constexpr int ASZ = 128 * ASTR;
    constexpr int BSZ = 32 * BSTR;
    constexpr int STG = ASZ + BSZ;
    extern __shared__ __half smemh[];

    const int wsel = blockIdx.x >> 3;
    const int n0 = (blockIdx.x & 7) * 128;
    const int m0 = blockIdx.y * 128;

    const __half* Bh = Wh + (long)wsel * HID * DIM;
    __half* Out = (wsel == 0) ? Qh : (wsel == 1) ? Kh : Vh;

    const int tid  = threadIdx.x;
    const int lane = tid & 31;
    const int wm   = ((tid >> 5) & 3) * 32;
    const int wn   = (tid >> 7) * 64;

    uint32_t aS[NSTG], bS[NSTG];
    #pragma unroll
    for (int s = 0; s < NSTG; ++s) {
        uint32_t base = smem_u32(smemh + s * STG);
        aS[s] = base;
        bS[s] = base + ASZ * 2;
    }

    auto issue = [&](int kt, int s) {
        if (kt < HID) {
            #pragma unroll
            for (int i = 0; i < 2; ++i) {
                int q = tid + i * 256;
                int r = q >> 2, c = (q & 3) * 8;
                uint32_t doff = (uint32_t)(r * ASTR + c) * 2;
                cpa16(aS[s] + doff, Xh + (long)(m0 + r) * HID + kt + c);
                int kk = q >> 4, nn = (q & 15) * 8;
                uint32_t boff = (uint32_t)(kk * BSTR + nn) * 2;
                cpa16(bS[s] + boff, Bh + (long)(kt + kk) * DIM + n0 + nn);
            }
        }
        CP_COMMIT();
    };

    ACC_DECL();
    GEMM_MAINLOOP(HID, true, false);

    #pragma unroll
    for (int mt = 0; mt < 2; ++mt) {
        #pragma unroll
        for (int nt = 0; nt < 8; ++nt) {
            int row = m0 + wm + mt * 16 + (lane >> 2);
            int col = n0 + wn + nt * 8 + (lane & 3) * 2;
            float* f = acc[mt][nt];
            *(__half2*)(Out + (long)row * DIM + col) =
                __floats2half2_rn(f[0], f[1]);
            *(__half2*)(Out + (long)(row + 8) * DIM + col) =
                __floats2half2_rn(f[2], f[3]);
        }
    }
}

// ---------------------------------------------------------------------------
// Scores GEMM (NT fp16, causal): P = Q @ K^T raw dot, fp32 out.
// ---------------------------------------------------------------------------
__global__ __launch_bounds__(256)
void gemm_scores(const __half* __restrict__ Qh, const __half* __restrict__ Kh,
                 float* __restrict__ P)
{
    constexpr int ASZ = 128 * ASTR;
    constexpr int STG = 2 * ASZ;
    extern __shared__ __half smemh[];

    const int m0 = blockIdx.y * 128;
    const int n0 = blockIdx.x * 128;
    if (n0 > m0 + 127) return;

    const long zoff = (long)blockIdx.z * SEQ * DIM;
    Qh += zoff; Kh += zoff;
    P += (long)blockIdx.z * SEQ * SEQ;

    const int tid  = threadIdx.x;
    const int lane = tid & 31;
    const int wm   = ((tid >> 5) & 3) * 32;
    const int wn   = (tid >> 7) * 64;
    const bool active = (n0 + wn) <= (m0 + wm + 31);

    uint32_t aS[NSTG], bS[NSTG];
    #pragma unroll
    for (int s = 0; s < NSTG; ++s) {
        uint32_t base = smem_u32(smemh + s * STG);
        aS[s] = base;
        bS[s] = base + ASZ * 2;
    }

    auto issue = [&](int kt, int s) {
        if (kt < DIM) {
            #pragma unroll
            for (int i = 0; i < 2; ++i) {
                int q = tid + i * 256;
                int r = q >> 2, c = (q & 3) * 8;
                uint32_t doff = (uint32_t)(r * ASTR + c) * 2;
                cpa16(aS[s] + doff, Qh + (long)(m0 + r) * DIM + kt + c);
                cpa16(bS[s] + doff, Kh + (long)(n0 + r) * DIM + kt + c);
            }
        }
        CP_COMMIT();
    };

    ACC_DECL();
    GEMM_MAINLOOP(DIM, active, true);

    if (active) {
        #pragma unroll
        for (int mt = 0; mt < 2; ++mt) {
            #pragma unroll
            for (int nt = 0; nt < 8; ++nt) {
                int row = m0 + wm + mt * 16 + (lane >> 2);
                int col = n0 + wn + nt * 8 + (lane & 3) * 2;
                float* f = acc[mt][nt];
                *(float2*)(P + (long)row * SEQ + col) = make_float2(f[0], f[1]);
                *(float2*)(P + (long)(row + 8) * SEQ + col) =
                    make_float2(f[2], f[3]);
            }
        }
    }
}

// ---------------------------------------------------------------------------
// PV GEMM (NN fp16, K bounded): out = rs[row] * (P_e @ V), fp32 out.
// P_e holds unnormalized exp values; rs = 1/rowsum applied in epilogue.
// Longest-K tiles scheduled first (m0 reversed) for wave balance.
// ---------------------------------------------------------------------------
__global__ __launch_bounds__(256)
void gemm_pv(const __half* __restrict__ Ph, const __half* __restrict__ Vh,
             const float* __restrict__ rs, float* __restrict__ Out)
{
    constexpr int ASZ = 128 * ASTR;
    constexpr int BSZ = 32 * BSTR;
    constexpr int STG = ASZ + BSZ;
    extern __shared__ __half smemh[];

    const int m0 = (int)(gridDim.y - 1 - blockIdx.y) * 128;  // longest first
    const int n0 = blockIdx.x * 128;

    Ph += (long)blockIdx.z * SEQ * SEQ;
    Vh += (long)blockIdx.z * SEQ * DIM;
    rs += (long)blockIdx.z * SEQ;
    Out += (long)blockIdx.z * SEQ * DIM;

    const int tid  = threadIdx.x;
    const int lane = tid & 31;
    const int wm   = ((tid >> 5) & 3) * 32;
    const int wn   = (tid >> 7) * 64;
    const int kEnd = m0 + 128;   // P zero beyond diagonal tile edge

    uint32_t aS[NSTG], bS[NSTG];
    #pragma unroll
    for (int s = 0; s < NSTG; ++s) {
        uint32_t base = smem_u32(smemh + s * STG);
        aS[s] = base;
        bS[s] = base + ASZ * 2;
    }

    auto issue = [&](int kt, int s) {
        if (kt < kEnd) {
            #pragma unroll
            for (int i = 0; i < 2; ++i) {
                int q = tid + i * 256;
                int r = q >> 2, c = (q & 3) * 8;
                uint32_t doff = (uint32_t)(r * ASTR + c) * 2;
                cpa16(aS[s] + doff, Ph + (long)(m0 + r) * SEQ + kt + c);
                int kk = q >> 4, nn = (q & 15) * 8;
                uint32_t boff = (uint32_t)(kk * BSTR + nn) * 2;
                cpa16(bS[s] + boff, Vh + (long)(kt + kk) * DIM + n0 + nn);
            }
        }
        CP_COMMIT();
    };

    ACC_DECL();
    GEMM_MAINLOOP(kEnd, true, false);

    #pragma unroll
    for (int mt = 0; mt < 2; ++mt) {
        int row = m0 + wm + mt * 16 + (lane >> 2);
        float s0 = rs[row];
        float s1 = rs[row + 8];
        #pragma unroll
        for (int nt = 0; nt < 8; ++nt) {
            int col = n0 + wn + nt * 8 + (lane & 3) * 2;
            float* f = acc[mt][nt];
            *(float2*)(Out + (long)row * DIM + col) =
                make_float2(f[0] * s0, f[1] * s0);
            *(float2*)(Out + (long)(row + 8) * DIM + col) =
                make_float2(f[2] * s1, f[3] * s1);
        }
    }
}

// ---------------------------------------------------------------------------
// Causal softmax, 2-pass: raw scores -> fp16 UNNORMALIZED exp values + 1/sum.
// Pass 1: vectorized unmasked max over complete float4 blocks below L,
//         scalar boundary. Pass 2: exp + fp16 store + sum. Tail zero-fill.
// ---------------------------------------------------------------------------
__global__ __launch_bounds__(256)
void softmax_causal(const float* __restrict__ P, __half* __restrict__ Ph,
                    float* __restrict__ rs)
{
    const int S = SEQ;
    const int i = blockIdx.x, b = blockIdx.y;
    const float* row = P + ((long)b * S + i) * S;
    __half* hrow = Ph + ((long)b * S + i) * S;

    __shared__ float buf[SEQ];
    __shared__ float red[256];
    const int tid = threadIdx.x;
    const int L = i + 1;
    const int full4 = L >> 2;            // complete float4 blocks below L
    const int kB = (i & ~127) + 128;     // PV read bound (multiple of 128)

    // pass 1: scaled load + max (no masking on complete blocks)
    float m = -3.0e38f;
    for (int j4 = tid; j4 < full4; j4 += 256) {
        float4 v = *(const float4*)(row + j4 * 4);
        v.x *= SCALE; v.y *= SCALE; v.z *= SCALE; v.w *= SCALE;
        *(float4*)(buf + j4 * 4) = v;
        m = fmaxf(m, fmaxf(fmaxf(v.x, v.y), fmaxf(v.z, v.w)));
    }
    {   // boundary scalars (0..3 elements)
        int jb = full4 * 4 + tid;
        if (tid < (L & 3)) {
            float v = row[jb] * SCALE;
            buf[jb] = v;
            m = fmaxf(m, v);
        }
    }
    red[tid] = m;
    __syncthreads();
    #pragma unroll
    for (int sd = 128; sd > 0; sd >>= 1) {
        if (tid < sd) red[tid] = fmaxf(red[tid], red[tid + sd]);
        __syncthreads();
    }
    m = red[0];
    __syncthreads();

    // pass 2: exp + unnormalized fp16 store + sum
    float sum = 0.f;
    for (int j4 = tid; j4 < full4; j4 += 256) {
        float4 v = *(const float4*)(buf + j4 * 4);
        v.x = __expf(v.x - m);
        v.y = __expf(v.y - m);
        v.z = __expf(v.z - m);
        v.w = __expf(v.w - m);
        sum += v.x + v.y + v.z + v.w;
        __half2 h0 = __floats2half2_rn(v.x, v.y);
        __half2 h1 = __floats2half2_rn(v.z, v.w);
        uint2 u;
        u.x = reinterpret_cast<uint32_t&>(h0);
        u.y = reinterpret_cast<uint32_t&>(h1);
        *(uint2*)(hrow + j4 * 4) = u;
    }
    {   // boundary scalars
        int jb = full4 * 4 + tid;
        if (tid < (L & 3)) {
            float e = __expf(buf[jb] - m);
            sum += e;
            hrow[jb] = __float2half_rn(e);
        }
    }
    // tail zero-fill [L, kB)
    for (int j = L + tid; j < kB; j += 256)
        hrow[j] = __float2half_rn(0.f);

    red[tid] = sum;
    __syncthreads();
    #pragma unroll
    for (int sd = 128; sd > 0; sd >>= 1) {
        if (tid < sd) red[tid] += red[tid + sd];
        __syncthreads();
    }
    if (tid == 0) rs[(long)b * S + i] = 1.0f / red[0];
}

// ---------------------------------------------------------------------------
extern "C" void kernel_launch(void* const* d_in, const int* in_sizes, int n_in,
                              void* d_out, int out_size)
{
    (void)in_sizes; (void)n_in; (void)out_size;
    const float* X  = (const float*)d_in[0];
    const float* Wq = (const float*)d_in[1];
    const float* Wk = (const float*)d_in[2];
    const float* Wv = (const float*)d_in[3];
    float* out = (float*)d_out;

    #define SYM(v, s) void* v; cudaGetSymbolAddress(&v, s)
    SYM(pP, g_P); SYM(pRs, g_rs); SYM(pXh, g_Xh); SYM(pWh, g_Wh);
    SYM(pQh, g_Qh); SYM(pKh, g_Kh); SYM(pVh, g_Vh); SYM(pPh, g_Ph);
    #undef SYM

    const int NN_SMEM = NSTG * (128 * ASTR + 32 * BSTR) * 2;   // 56832 B
    const int NT_SMEM = NSTG * (2 * 128 * ASTR) * 2;           // 61440 B

    cudaFuncSetAttribute(gemm_qkv, cudaFuncAttributeMaxDynamicSharedMemorySize,
                         NN_SMEM);
    cudaFuncSetAttribute(gemm_scores, cudaFuncAttributeMaxDynamicSharedMemorySize,
                         NT_SMEM);
    cudaFuncSetAttribute(gemm_pv, cudaFuncAttributeMaxDynamicSharedMemorySize,
                         NN_SMEM);

    // 0) fused fp16 quantization of X, Wq, Wk, Wv
    {
        long nX4 = (long)BATCH * SEQ * HID / 4;
        long nW4 = (long)HID * DIM / 4;
        quant_all<<<2960, 256>>>(X, Wq, Wk, Wv, (__half*)pXh, (__half*)pWh,
                                 nX4, nW4);
    }

    // 1) merged QKV projections (fp16) -> fp16 Q, K, V
    {
        dim3 grid(24, (BATCH * SEQ) / 128, 1);
        gemm_qkv<<<grid, 256, NN_SMEM>>>(
            (__half*)pXh, (__half*)pWh,
            (__half*)pQh, (__half*)pKh, (__half*)pVh);
    }

    // 2) raw scores = Q @ K^T (fp16), causal blocks only
    {
        dim3 grid(SEQ / 128, SEQ / 128, BATCH);
        gemm_scores<<<grid, 256, NT_SMEM>>>(
            (__half*)pQh, (__half*)pKh, (float*)pP);
    }

    // 3) causal softmax (2-pass, unnormalized e + 1/sum)
    {
        dim3 grid(SEQ, BATCH);
        softmax_causal<<<grid, 256>>>((float*)pP, (__half*)pPh, (float*)pRs);
    }

    // 4) out = rs * (P_e @ V), K bounded by causality, longest tiles first
    {
        dim3 grid(DIM / 128, SEQ / 128, BATCH);
        gemm_pv<<<grid, 256, NN_SMEM>>>(
            (__half*)pPh, (__half*)pVh, (float*)pRs, out);
    }
}

// round 16
// speedup vs baseline: 1.0566x; 1.0099x over previous
#include <cuda_runtime.h>
#include <cuda_fp16.h>
#include <cstdint>
#include <math.h>

#define BATCH 4
#define SEQ   2048
#define HID   1024
#define DIM   1024
#define SCALE 0.03125f   // 1/sqrt(1024)

// Scratch (device globals; runtime allocation is forbidden)
__device__ float  g_P [(long)BATCH * SEQ * SEQ];
__device__ float  g_rs[(long)BATCH * SEQ];       // per-row 1/sum
__device__ __half g_Xh[(long)BATCH * SEQ * HID];
__device__ __half g_Wh[(long)3 * HID * DIM];     // Wq,Wk,Wv stacked, [H][D] each
__device__ __half g_Qh[(long)BATCH * SEQ * DIM];
__device__ __half g_Kh[(long)BATCH * SEQ * DIM];
__device__ __half g_Vh[(long)BATCH * SEQ * DIM];
__device__ __half g_Ph[(long)BATCH * SEQ * SEQ];

// ---------------------------------------------------------------------------
// PTX helpers (baseline sm_80-level PTX)
// ---------------------------------------------------------------------------
__device__ __forceinline__ uint32_t smem_u32(const void* p) {
    uint32_t a;
    asm("{ .reg .u64 t; cvta.to.shared.u64 t, %1; cvt.u32.u64 %0, t; }"
        : "=r"(a) : "l"(p));
    return a;
}
__device__ __forceinline__ void cpa16(uint32_t dst, const void* src) {
    asm volatile("cp.async.cg.shared.global [%0], [%1], 16;" :: "r"(dst), "l"(src));
}
#define CP_COMMIT() asm volatile("cp.async.commit_group;" ::: "memory")
#define CP_WAIT1()  asm volatile("cp.async.wait_group 1;" ::: "memory")

__device__ __forceinline__ void ldsm_x4(uint32_t* r, uint32_t addr) {
    asm volatile("ldmatrix.sync.aligned.m8n8.x4.shared.b16 {%0,%1,%2,%3}, [%4];"
                 : "=r"(r[0]), "=r"(r[1]), "=r"(r[2]), "=r"(r[3]) : "r"(addr));
}
__device__ __forceinline__ void ldsm_x4_t(uint32_t* r, uint32_t addr) {
    asm volatile("ldmatrix.sync.aligned.m8n8.x4.trans.shared.b16 {%0,%1,%2,%3}, [%4];"
                 : "=r"(r[0]), "=r"(r[1]), "=r"(r[2]), "=r"(r[3]) : "r"(addr));
}
__device__ __forceinline__ void mma_f16(float* c, const uint32_t* a,
                                        const uint32_t* b) {
    asm volatile(
        "mma.sync.aligned.m16n8k16.row.col.f32.f16.f16.f32 "
        "{%0,%1,%2,%3}, {%4,%5,%6,%7}, {%8,%9}, {%0,%1,%2,%3};"
        : "+f"(c[0]), "+f"(c[1]), "+f"(c[2]), "+f"(c[3])
        : "r"(a[0]), "r"(a[1]), "r"(a[2]), "r"(a[3]), "r"(b[0]), "r"(b[1]));
}

// ---------------------------------------------------------------------------
// Fused fp32 -> fp16 quantize for X, Wq, Wk, Wv in one launch.
// ---------------------------------------------------------------------------
__global__ __launch_bounds__(256)
void quant_all(const float* __restrict__ X, const float* __restrict__ Wq,
               const float* __restrict__ Wk, const float* __restrict__ Wv,
               __half* __restrict__ Xh, __half* __restrict__ Wh,
               long nX4, long nW4)
{
    long total = nX4 + 3 * nW4;
    long i = blockIdx.x * 256 + threadIdx.x;
    long stride = (long)gridDim.x * 256;
    for (; i < total; i += stride) {
        const float* src;
        __half* dst;
        long j;
        if (i < nX4) {
            src = X; dst = Xh; j = i;
        } else {
            long k = i - nX4;
            int w = (int)(k / nW4);
            j = k - (long)w * nW4;
            src = (w == 0) ? Wq : (w == 1) ? Wk : Wv;
            dst = Wh + (long)w * HID * DIM;
        }
        float4 v = *(const float4*)(src + j * 4);
        __half2 h0 = __floats2half2_rn(v.x, v.y);
        __half2 h1 = __floats2half2_rn(v.z, v.w);
        uint2 u;
        u.x = reinterpret_cast<uint32_t&>(h0);
        u.y = reinterpret_cast<uint32_t&>(h1);
        *(uint2*)(dst + j * 4) = u;
    }
}

// ---------------------------------------------------------------------------
// Tiling config: BM=BN=128, BK=32, 256 threads, 8 warps (4m x 2n),
// warp tile 32x64. 3-stage cp.async pipeline, one barrier per k-iter.
// ---------------------------------------------------------------------------
#define ASTR 40
#define BSTR 136
#define NSTG 3

template <bool TRANSB>
__device__ __forceinline__ void mma_tile1(
    float acc[2][8][4], uint32_t aS, uint32_t bS, int wm, int wn, int lane)
{
    #pragma unroll
    for (int ks = 0; ks < 2; ++ks) {
        uint32_t aF[2][4];
        #pragma unroll
        for (int mt = 0; mt < 2; ++mt) {
            uint32_t off =
                ((uint32_t)(wm + mt * 16 + (lane & 15)) * ASTR +
                 ks * 16 + (lane >> 4) * 8) * 2;
            ldsm_x4(aF[mt], aS + off);
        }
        #pragma unroll
        for (int np = 0; np < 4; ++np) {
            uint32_t bF[4];
            if (TRANSB) {
                uint32_t nrow = wn + np * 16 + (lane & 7) + (lane >> 4) * 8;
                uint32_t off = (nrow * ASTR + ks * 16 + ((lane >> 3) & 1) * 8) * 2;
                ldsm_x4(bF, bS + off);
            } else {
                uint32_t krow = ks * 16 + (lane & 15);
                uint32_t ncol = wn + np * 16 + (lane >> 4) * 8;
                uint32_t off = (krow * BSTR + ncol) * 2;
                ldsm_x4_t(bF, bS + off);
            }
            #pragma unroll
            for (int h = 0; h < 2; ++h) {
                #pragma unroll
                for (int mt = 0; mt < 2; ++mt)
                    mma_f16(acc[mt][np * 2 + h], aF[mt], bF + h * 2);
            }
        }
    }
}

#define ACC_DECL()                                                          \
    float acc[2][8][4];                                                     \
    _Pragma("unroll")                                                       \
    for (int i_ = 0; i_ < 2; ++i_)                                          \
        _Pragma("unroll")                                                   \
        for (int j_ = 0; j_ < 8; ++j_)                                      \
            _Pragma("unroll")                                               \
            for (int t_ = 0; t_ < 4; ++t_) acc[i_][j_][t_] = 0.f;

#define GEMM_MAINLOOP(KEND, ACTIVE, TRANSB_)                                \
    issue(0, 0);                                                            \
    issue(32, 1);                                                            \
    {                                                                       \
        int s = 0;                                                          \
        for (int kt = 0; kt < (KEND); kt += 32) {                           \
            CP_WAIT1();                                                     \
            __syncthreads();                                                \
            issue(kt + 64, (s + 2) % NSTG);                                 \
            if (ACTIVE)                                                     \
                mma_tile1<TRANSB_>(acc, aS[s], bS[s], wm, wn, lane);        \
            s = (s + 1) % NSTG;                                             \
        }                                                                   \
    }

// ---------------------------------------------------------------------------
// Merged QKV projection (fp16 NN): grid (24, 64). bx>>3 selects W/output.
// ---------------------------------------------------------------------------
__global__ __launch_bounds__(256)
void gemm_qkv(const __half* __restrict__ Xh, const __half* __restrict__ Wh,
              __half* __restrict__ Qh, __half* __restrict__ Kh,
              __half* __restrict__ Vh)
{
    constexpr int ASZ = 128 * ASTR;
    constexpr int BSZ = 32 * BSTR;
    constexpr int STG = ASZ + BSZ;
    extern __shared__ __half smemh[];

    const int wsel = blockIdx.x >> 3;
    const int n0 = (blockIdx.x & 7) * 128;
    const int m0 = blockIdx.y * 128;

    const __half* Bh = Wh + (long)wsel * HID * DIM;
    __half* Out = (wsel == 0) ? Qh : (wsel == 1) ? Kh : Vh;

    const int tid  = threadIdx.x;
    const int lane = tid & 31;
    const int wm   = ((tid >> 5) & 3) * 32;
    const int wn   = (tid >> 7) * 64;

    uint32_t aS[NSTG], bS[NSTG];
    #pragma unroll
    for (int s = 0; s < NSTG; ++s) {
        uint32_t base = smem_u32(smemh + s * STG);
        aS[s] = base;
        bS[s] = base + ASZ * 2;
    }

    auto issue = [&](int kt, int s) {
        if (kt < HID) {
            #pragma unroll
            for (int i = 0; i < 2; ++i) {
                int q = tid + i * 256;
                int r = q >> 2, c = (q & 3) * 8;
                uint32_t doff = (uint32_t)(r * ASTR + c) * 2;
                cpa16(aS[s] + doff, Xh + (long)(m0 + r) * HID + kt + c);
                int kk = q >> 4, nn = (q & 15) * 8;
                uint32_t boff = (uint32_t)(kk * BSTR + nn) * 2;
                cpa16(bS[s] + boff, Bh + (long)(kt + kk) * DIM + n0 + nn);
            }
        }
        CP_COMMIT();
    };

    ACC_DECL();
    GEMM_MAINLOOP(HID, true, false);

    #pragma unroll
    for (int mt = 0; mt < 2; ++mt) {
        #pragma unroll
        for (int nt = 0; nt < 8; ++nt) {
            int row = m0 + wm + mt * 16 + (lane >> 2);
            int col = n0 + wn + nt * 8 + (lane & 3) * 2;
            float* f = acc[mt][nt];
            *(__half2*)(Out + (long)row * DIM + col) =
                __floats2half2_rn(f[0], f[1]);
            *(__half2*)(Out + (long)(row + 8) * DIM + col) =
                __floats2half2_rn(f[2], f[3]);
        }
    }
}

// ---------------------------------------------------------------------------
// Scores GEMM (NT fp16, causal): P = Q @ K^T raw dot, fp32 out.
// ---------------------------------------------------------------------------
__global__ __launch_bounds__(256)
void gemm_scores(const __half* __restrict__ Qh, const __half* __restrict__ Kh,
                 float* __restrict__ P)
{
    constexpr int ASZ = 128 * ASTR;
    constexpr int STG = 2 * ASZ;
    extern __shared__ __half smemh[];

    const int m0 = blockIdx.y * 128;
    const int n0 = blockIdx.x * 128;
    if (n0 > m0 + 127) return;

    const long zoff = (long)blockIdx.z * SEQ * DIM;
    Qh += zoff; Kh += zoff;
    P += (long)blockIdx.z * SEQ * SEQ;

    const int tid  = threadIdx.x;
    const int lane = tid & 31;
    const int wm   = ((tid >> 5) & 3) * 32;
    const int wn   = (tid >> 7) * 64;
    const bool active = (n0 + wn) <= (m0 + wm + 31);

    uint32_t aS[NSTG], bS[NSTG];
    #pragma unroll
    for (int s = 0; s < NSTG; ++s) {
        uint32_t base = smem_u32(smemh + s * STG);
        aS[s] = base;
        bS[s] = base + ASZ * 2;
    }

    auto issue = [&](int kt, int s) {
        if (kt < DIM) {
            #pragma unroll
            for (int i = 0; i < 2; ++i) {
                int q = tid + i * 256;
                int r = q >> 2, c = (q & 3) * 8;
                uint32_t doff = (uint32_t)(r * ASTR + c) * 2;
                cpa16(aS[s] + doff, Qh + (long)(m0 + r) * DIM + kt + c);
                cpa16(bS[s] + doff, Kh + (long)(n0 + r) * DIM + kt + c);
            }
        }
        CP_COMMIT();
    };

    ACC_DECL();
    GEMM_MAINLOOP(DIM, active, true);

    if (active) {
        #pragma unroll
        for (int mt = 0; mt < 2; ++mt) {
            #pragma unroll
            for (int nt = 0; nt < 8; ++nt) {
                int row = m0 + wm + mt * 16 + (lane >> 2);
                int col = n0 + wn + nt * 8 + (lane & 3) * 2;
                float* f = acc[mt][nt];
                *(float2*)(P + (long)row * SEQ + col) = make_float2(f[0], f[1]);
                *(float2*)(P + (long)(row + 8) * SEQ + col) =
                    make_float2(f[2], f[3]);
            }
        }
    }
}

// ---------------------------------------------------------------------------
// PV GEMM (NN fp16, K bounded): out = rs[row] * (P_e @ V), fp32 out.
// Longest-K tiles scheduled first (m0 reversed) for wave balance.
// ---------------------------------------------------------------------------
__global__ __launch_bounds__(256)
void gemm_pv(const __half* __restrict__ Ph, const __half* __restrict__ Vh,
             const float* __restrict__ rs, float* __restrict__ Out)
{
    constexpr int ASZ = 128 * ASTR;
    constexpr int BSZ = 32 * BSTR;
    constexpr int STG = ASZ + BSZ;
    extern __shared__ __half smemh[];

    const int m0 = (int)(gridDim.y - 1 - blockIdx.y) * 128;  // longest first
    const int n0 = blockIdx.x * 128;

    Ph += (long)blockIdx.z * SEQ * SEQ;
    Vh += (long)blockIdx.z * SEQ * DIM;
    rs += (long)blockIdx.z * SEQ;
    Out += (long)blockIdx.z * SEQ * DIM;

    const int tid  = threadIdx.x;
    const int lane = tid & 31;
    const int wm   = ((tid >> 5) & 3) * 32;
    const int wn   = (tid >> 7) * 64;
    const int kEnd = m0 + 128;   // P zero beyond diagonal tile edge

    uint32_t aS[NSTG], bS[NSTG];
    #pragma unroll
    for (int s = 0; s < NSTG; ++s) {
        uint32_t base = smem_u32(smemh + s * STG);
        aS[s] = base;
        bS[s] = base + ASZ * 2;
    }

    auto issue = [&](int kt, int s) {
        if (kt < kEnd) {
            #pragma unroll
            for (int i = 0; i < 2; ++i) {
                int q = tid + i * 256;
                int r = q >> 2, c = (q & 3) * 8;
                uint32_t doff = (uint32_t)(r * ASTR + c) * 2;
                cpa16(aS[s] + doff, Ph + (long)(m0 + r) * SEQ + kt + c);
                int kk = q >> 4, nn = (q & 15) * 8;
                uint32_t boff = (uint32_t)(kk * BSTR + nn) * 2;
                cpa16(bS[s] + boff, Vh + (long)(kt + kk) * DIM + n0 + nn);
            }
        }
        CP_COMMIT();
    };

    ACC_DECL();
    GEMM_MAINLOOP(kEnd, true, false);

    #pragma unroll
    for (int mt = 0; mt < 2; ++mt) {
        int row = m0 + wm + mt * 16 + (lane >> 2);
        float s0 = rs[row];
        float s1 = rs[row + 8];
        #pragma unroll
        for (int nt = 0; nt < 8; ++nt) {
            int col = n0 + wn + nt * 8 + (lane & 3) * 2;
            float* f = acc[mt][nt];
            *(float2*)(Out + (long)row * DIM + col) =
                make_float2(f[0] * s0, f[1] * s0);
            *(float2*)(Out + (long)(row + 8) * DIM + col) =
                make_float2(f[2] * s1, f[3] * s1);
        }
    }
}

// ---------------------------------------------------------------------------
// Causal softmax, 2-pass, smem-free row data (P row is L2-resident on the
// second read). Warp-shuffle reductions (2 barriers total per reduction).
// Outputs UNNORMALIZED e in fp16 + per-row 1/sum (applied in PV epilogue).
// ---------------------------------------------------------------------------
__device__ __forceinline__ float warp_max(float v) {
    #pragma unroll
    for (int o = 16; o > 0; o >>= 1)
        v = fmaxf(v, __shfl_xor_sync(0xffffffffu, v, o));
    return v;
}
__device__ __forceinline__ float warp_sum(float v) {
    #pragma unroll
    for (int o = 16; o > 0; o >>= 1)
        v += __shfl_xor_sync(0xffffffffu, v, o);
    return v;
}

__global__ __launch_bounds__(256)
void softmax_causal(const float* __restrict__ P, __half* __restrict__ Ph,
                    float* __restrict__ rs)
{
    const int S = SEQ;
    const int i = blockIdx.x, b = blockIdx.y;
    const float* row = P + ((long)b * S + i) * S;
    __half* hrow = Ph + ((long)b * S + i) * S;

    __shared__ float red[8];
    const int tid = threadIdx.x;
    const int lane = tid & 31;
    const int wid = tid >> 5;
    const int L = i + 1;
    const int full4 = L >> 2;            // complete float4 blocks below L
    const int kB = (i & ~127) + 128;     // PV read bound (multiple of 128)

    // ---- pass 1: max of scaled scores (global reads only) ----
    float m = -3.0e38f;
    for (int j4 = tid; j4 < full4; j4 += 256) {
        float4 v = *(const float4*)(row + j4 * 4);
        m = fmaxf(m, fmaxf(fmaxf(v.x, v.y), fmaxf(v.z, v.w)));
    }
    {
        int jb = full4 * 4 + tid;
        if (tid < (L & 3)) m = fmaxf(m, row[jb]);
    }
    m = warp_max(m);
    if (lane == 0) red[wid] = m;
    __syncthreads();
    if (wid == 0) {
        float t = (lane < 8) ? red[lane] : -3.0e38f;
        t = warp_max(t);
        if (lane == 0) red[0] = t;
    }
    __syncthreads();
    m = red[0] * SCALE;
    __syncthreads();

    // ---- pass 2: exp + fp16 store + sum (row re-read hits L2) ----
    float sum = 0.f;
    for (int j4 = tid; j4 < full4; j4 += 256) {
        float4 v = *(const float4*)(row + j4 * 4);
        v.x = __expf(fmaf(v.x, SCALE, -m));
        v.y = __expf(fmaf(v.y, SCALE, -m));
        v.z = __expf(fmaf(v.z, SCALE, -m));
        v.w = __expf(fmaf(v.w, SCALE, -m));
        sum += v.x + v.y + v.z + v.w;
        __half2 h0 = __floats2half2_rn(v.x, v.y);
        __half2 h1 = __floats2half2_rn(v.z, v.w);
        uint2 u;
        u.x = reinterpret_cast<uint32_t&>(h0);
        u.y = reinterpret_cast<uint32_t&>(h1);
        *(uint2*)(hrow + j4 * 4) = u;
    }
    {
        int jb = full4 * 4 + tid;
        if (tid < (L & 3)) {
            float e = __expf(fmaf(row[jb], SCALE, -m));
            sum += e;
            hrow[jb] = __float2half_rn(e);
        }
    }
    // tail zero-fill [L, kB)
    for (int j = L + tid; j < kB; j += 256)
        hrow[j] = __float2half_rn(0.f);

    sum = warp_sum(sum);
    if (lane == 0) red[wid] = sum;
    __syncthreads();
    if (wid == 0) {
        float t = (lane < 8) ? red[lane] : 0.f;
        t = warp_sum(t);
        if (lane == 0) rs[(long)b * S + i] = 1.0f / t;
    }
}

// ---------------------------------------------------------------------------
extern "C" void kernel_launch(void* const* d_in, const int* in_sizes, int n_in,
                              void* d_out, int out_size)
{
    (void)in_sizes; (void)n_in; (void)out_size;
    const float* X  = (const float*)d_in[0];
    const float* Wq = (const float*)d_in[1];
    const float* Wk = (const float*)d_in[2];
    const float* Wv = (const float*)d_in[3];
    float* out = (float*)d_out;

    #define SYM(v, s) void* v; cudaGetSymbolAddress(&v, s)
    SYM(pP, g_P); SYM(pRs, g_rs); SYM(pXh, g_Xh); SYM(pWh, g_Wh);
    SYM(pQh, g_Qh); SYM(pKh, g_Kh); SYM(pVh, g_Vh); SYM(pPh, g_Ph);
    #undef SYM

    const int NN_SMEM = NSTG * (128 * ASTR + 32 * BSTR) * 2;   // 56832 B
    const int NT_SMEM = NSTG * (2 * 128 * ASTR) * 2;           // 61440 B

    cudaFuncSetAttribute(gemm_qkv, cudaFuncAttributeMaxDynamicSharedMemorySize,
                         NN_SMEM);
    cudaFuncSetAttribute(gemm_scores, cudaFuncAttributeMaxDynamicSharedMemorySize,
                         NT_SMEM);
    cudaFuncSetAttribute(gemm_pv, cudaFuncAttributeMaxDynamicSharedMemorySize,
                         NN_SMEM);

    // 0) fused fp16 quantization of X, Wq, Wk, Wv
    {
        long nX4 = (long)BATCH * SEQ * HID / 4;
        long nW4 = (long)HID * DIM / 4;
        quant_all<<<2960, 256>>>(X, Wq, Wk, Wv, (__half*)pXh, (__half*)pWh,
                                 nX4, nW4);
    }

    // 1) merged QKV projections (fp16) -> fp16 Q, K, V
    {
        dim3 grid(24, (BATCH * SEQ) / 128, 1);
        gemm_qkv<<<grid, 256, NN_SMEM>>>(
            (__half*)pXh, (__half*)pWh,
            (__half*)pQh, (__half*)pKh, (__half*)pVh);
    }

    // 2) raw scores = Q @ K^T (fp16), causal blocks only
    {
        dim3 grid(SEQ / 128, SEQ / 128, BATCH);
        gemm_scores<<<grid, 256, NT_SMEM>>>(
            (__half*)pQh, (__half*)pKh, (float*)pP);
    }

    // 3) causal softmax (2-pass, smem-free, shuffle reductions)
    {
        dim3 grid(SEQ, BATCH);
        softmax_causal<<<grid, 256>>>((float*)pP, (__half*)pPh, (float*)pRs);
    }

    // 4) out = rs * (P_e @ V), K bounded by causality, longest tiles first
    {
        dim3 grid(DIM / 128, SEQ / 128, BATCH);
        gemm_pv<<<grid, 256, NN_SMEM>>>(
            (__half*)pPh, (__half*)pVh, (float*)pRs, out);
    }
}

// round 17
// speedup vs baseline: 1.0648x; 1.0077x over previous
#include <cuda_runtime.h>
#include <cuda_fp16.h>
#include <cstdint>
#include <math.h>

#define BATCH 4
#define SEQ   2048
#define HID   1024
#define DIM   1024
#define SCALE 0.03125f   // 1/sqrt(1024)

// Scratch (device globals; runtime allocation is forbidden)
__device__ float    g_P [(long)BATCH * SEQ * SEQ];
__device__ float    g_rs[(long)BATCH * SEQ];     // per-row 1/sum
__device__ unsigned g_rm[(long)BATCH * SEQ];     // per-row max (ordered-uint enc)
__device__ __half   g_Xh[(long)BATCH * SEQ * HID];
__device__ __half   g_Wh[(long)3 * HID * DIM];   // Wq,Wk,Wv stacked
__device__ __half   g_Qh[(long)BATCH * SEQ * DIM];
__device__ __half   g_Kh[(long)BATCH * SEQ * DIM];
__device__ __half   g_Vh[(long)BATCH * SEQ * DIM];
__device__ __half   g_Ph[(long)BATCH * SEQ * SEQ];

// ---------------------------------------------------------------------------
// PTX helpers (baseline sm_80-level PTX)
// ---------------------------------------------------------------------------
__device__ __forceinline__ uint32_t smem_u32(const void* p) {
    uint32_t a;
    asm("{ .reg .u64 t; cvta.to.shared.u64 t, %1; cvt.u32.u64 %0, t; }"
        : "=r"(a) : "l"(p));
    return a;
}
__device__ __forceinline__ void cpa16(uint32_t dst, const void* src) {
    asm volatile("cp.async.cg.shared.global [%0], [%1], 16;" :: "r"(dst), "l"(src));
}
#define CP_COMMIT() asm volatile("cp.async.commit_group;" ::: "memory")
#define CP_WAIT1()  asm volatile("cp.async.wait_group 1;" ::: "memory")

__device__ __forceinline__ void ldsm_x4(uint32_t* r, uint32_t addr) {
    asm volatile("ldmatrix.sync.aligned.m8n8.x4.shared.b16 {%0,%1,%2,%3}, [%4];"
                 : "=r"(r[0]), "=r"(r[1]), "=r"(r[2]), "=r"(r[3]) : "r"(addr));
}
__device__ __forceinline__ void ldsm_x4_t(uint32_t* r, uint32_t addr) {
    asm volatile("ldmatrix.sync.aligned.m8n8.x4.trans.shared.b16 {%0,%1,%2,%3}, [%4];"
                 : "=r"(r[0]), "=r"(r[1]), "=r"(r[2]), "=r"(r[3]) : "r"(addr));
}
__device__ __forceinline__ void mma_f16(float* c, const uint32_t* a,
                                        const uint32_t* b) {
    asm volatile(
        "mma.sync.aligned.m16n8k16.row.col.f32.f16.f16.f32 "
        "{%0,%1,%2,%3}, {%4,%5,%6,%7}, {%8,%9}, {%0,%1,%2,%3};"
        : "+f"(c[0]), "+f"(c[1]), "+f"(c[2]), "+f"(c[3])
        : "r"(a[0]), "r"(a[1]), "r"(a[2]), "r"(a[3]), "r"(b[0]), "r"(b[1]));
}

// ordered-uint encoding of float: monotonic, atomicMax(unsigned)-compatible
__device__ __forceinline__ unsigned fenc(float f) {
    unsigned u = __float_as_uint(f);
    return (u & 0x80000000u) ? ~u : (u | 0x80000000u);
}
__device__ __forceinline__ float fdec(unsigned u) {
    u = (u & 0x80000000u) ? (u & 0x7fffffffu) : ~u;
    return __uint_as_float(u);
}

// ---------------------------------------------------------------------------
// Fused fp32 -> fp16 quantize for X, Wq, Wk, Wv + zero-init of row-max buffer.
// ---------------------------------------------------------------------------
__global__ __launch_bounds__(256)
void quant_all(const float* __restrict__ X, const float* __restrict__ Wq,
               const float* __restrict__ Wk, const float* __restrict__ Wv,
               __half* __restrict__ Xh, __half* __restrict__ Wh,
               unsigned* __restrict__ rm, long nX4, long nW4)
{
    long total = nX4 + 3 * nW4;
    long i = blockIdx.x * 256 + threadIdx.x;
    long stride = (long)gridDim.x * 256;
    // row-max init (8192 entries; enc floor is > 0, so 0 is below all values)
    for (long t = i; t < (long)BATCH * SEQ; t += stride) rm[t] = 0u;
    for (; i < total; i += stride) {
        const float* src;
        __half* dst;
        long j;
        if (i < nX4) {
            src = X; dst = Xh; j = i;
        } else {
            long k = i - nX4;
            int w = (int)(k / nW4);
            j = k - (long)w * nW4;
            src = (w == 0) ? Wq : (w == 1) ? Wk : Wv;
            dst = Wh + (long)w * HID * DIM;
        }
        float4 v = *(const float4*)(src + j * 4);
        __half2 h0 = __floats2half2_rn(v.x, v.y);
        __half2 h1 = __floats2half2_rn(v.z, v.w);
        uint2 u;
        u.x = reinterpret_cast<uint32_t&>(h0);
        u.y = reinterpret_cast<uint32_t&>(h1);
        *(uint2*)(dst + j * 4) = u;
    }
}

// ---------------------------------------------------------------------------
// Tiling config: BM=BN=128, BK=32, 256 threads, 8 warps (4m x 2n),
// warp tile 32x64. 3-stage cp.async pipeline, one barrier per k-iter.
// ---------------------------------------------------------------------------
#define ASTR 40
#define BSTR 136
#define NSTG 3

template <bool TRANSB>
__device__ __forceinline__ void mma_tile1(
    float acc[2][8][4], uint32_t aS, uint32_t bS, int wm, int wn, int lane)
{
    #pragma unroll
    for (int ks = 0; ks < 2; ++ks) {
        uint32_t aF[2][4];
        #pragma unroll
        for (int mt = 0; mt < 2; ++mt) {
            uint32_t off =
                ((uint32_t)(wm + mt * 16 + (lane & 15)) * ASTR +
                 ks * 16 + (lane >> 4) * 8) * 2;
            ldsm_x4(aF[mt], aS + off);
        }
        #pragma unroll
        for (int np = 0; np < 4; ++np) {
            uint32_t bF[4];
            if (TRANSB) {
                uint32_t nrow = wn + np * 16 + (lane & 7) + (lane >> 4) * 8;
                uint32_t off = (nrow * ASTR + ks * 16 + ((lane >> 3) & 1) * 8) * 2;
                ldsm_x4(bF, bS + off);
            } else {
                uint32_t krow = ks * 16 + (lane & 15);
                uint32_t ncol = wn + np * 16 + (lane >> 4) * 8;
                uint32_t off = (krow * BSTR + ncol) * 2;
                ldsm_x4_t(bF, bS + off);
            }
            #pragma unroll
            for (int h = 0; h < 2; ++h) {
                #pragma unroll
                for (int mt = 0; mt < 2; ++mt)
                    mma_f16(acc[mt][np * 2 + h], aF[mt], bF + h * 2);
            }
        }
    }
}

#define ACC_DECL()                                                          \
    float acc[2][8][4];                                                     \
    _Pragma("unroll")                                                       \
    for (int i_ = 0; i_ < 2; ++i_)                                          \
        _Pragma("unroll")                                                   \
        for (int j_ = 0; j_ < 8; ++j_)                                      \
            _Pragma("unroll")                                               \
            for (int t_ = 0; t_ < 4; ++t_) acc[i_][j_][t_] = 0.f;

#define GEMM_MAINLOOP(KEND, ACTIVE, TRANSB_)                                \
    issue(0, 0);                                                            \
    issue(32, 1);                                                            \
    {                                                                       \
        int s = 0;                                                          \
        for (int kt = 0; kt < (KEND); kt += 32) {                           \
            CP_WAIT1();                                                     \
            __syncthreads();                                                \
            issue(kt + 64, (s + 2) % NSTG);                                 \
            if (ACTIVE)                                                     \
                mma_tile1<TRANSB_>(acc, aS[s], bS[s], wm, wn, lane);        \
            s = (s + 1) % NSTG;                                             \
        }                                                                   \
    }

// ---------------------------------------------------------------------------
// Merged QKV projection (fp16 NN): grid (24, 64). bx>>3 selects W/output.
// ---------------------------------------------------------------------------
__global__ __launch_bounds__(256)
void gemm_qkv(const __half* __restrict__ Xh, const __half* __restrict__ Wh,
              __half* __restrict__ Qh, __half* __restrict__ Kh,
              __half* __restrict__ Vh)
{
    constexpr int ASZ = 128 * ASTR;
    constexpr int BSZ = 32 * BSTR;
    constexpr int STG = ASZ + BSZ;
    extern __shared__ __half smemh[];

    const int wsel = blockIdx.x >> 3;
    const int n0 = (blockIdx.x & 7) * 128;
    const int m0 = blockIdx.y * 128;

    const __half* Bh = Wh + (long)wsel * HID * DIM;
    __half* Out = (wsel == 0) ? Qh : (wsel == 1) ? Kh : Vh;

    const int tid  = threadIdx.x;
    const int lane = tid & 31;
    const int wm   = ((tid >> 5) & 3) * 32;
    const int wn   = (tid >> 7) * 64;

    uint32_t aS[NSTG], bS[NSTG];
    #pragma unroll
    for (int s = 0; s < NSTG; ++s) {
        uint32_t base = smem_u32(smemh + s * STG);
        aS[s] = base;
        bS[s] = base + ASZ * 2;
    }

    auto issue = [&](int kt, int s) {
        if (kt < HID) {
            #pragma unroll
            for (int i = 0; i < 2; ++i) {
                int q = tid + i * 256;
                int r = q >> 2, c = (q & 3) * 8;
                uint32_t doff = (uint32_t)(r * ASTR + c) * 2;
                cpa16(aS[s] + doff, Xh + (long)(m0 + r) * HID + kt + c);
                int kk = q >> 4, nn = (q & 15) * 8;
                uint32_t boff = (uint32_t)(kk * BSTR + nn) * 2;
                cpa16(bS[s] + boff, Bh + (long)(kt + kk) * DIM + n0 + nn);
            }
        }
        CP_COMMIT();
    };

    ACC_DECL();
    GEMM_MAINLOOP(HID, true, false);

    #pragma unroll
    for (int mt = 0; mt < 2; ++mt) {
        #pragma unroll
        for (int nt = 0; nt < 8; ++nt) {
            int row = m0 + wm + mt * 16 + (lane >> 2);
            int col = n0 + wn + nt * 8 + (lane & 3) * 2;
            float* f = acc[mt][nt];
            *(__half2*)(Out + (long)row * DIM + col) =
                __floats2half2_rn(f[0], f[1]);
            *(__half2*)(Out + (long)(row + 8) * DIM + col) =
                __floats2half2_rn(f[2], f[3]);
        }
    }
}

// ---------------------------------------------------------------------------
// Scores GEMM (NT fp16, causal): P = Q @ K^T raw dot, fp32 out.
// Fused per-row masked max -> atomicMax into rm (ordered-uint encoding).
// ---------------------------------------------------------------------------
__global__ __launch_bounds__(256)
void gemm_scores(const __half* __restrict__ Qh, const __half* __restrict__ Kh,
                 float* __restrict__ P, unsigned* __restrict__ rm)
{
    constexpr int ASZ = 128 * ASTR;
    constexpr int STG = 2 * ASZ;
    extern __shared__ __half smemh[];

    const int m0 = blockIdx.y * 128;
    const int n0 = blockIdx.x * 128;
    if (n0 > m0 + 127) return;

    const long zoff = (long)blockIdx.z * SEQ * DIM;
    Qh += zoff; Kh += zoff;
    P += (long)blockIdx.z * SEQ * SEQ;
    rm += (long)blockIdx.z * SEQ;

    const int tid  = threadIdx.x;
    const int lane = tid & 31;
    const int wm   = ((tid >> 5) & 3) * 32;
    const int wn   = (tid >> 7) * 64;
    const bool active = (n0 + wn) <= (m0 + wm + 31);
    const bool diag = (m0 == n0);

    uint32_t aS[NSTG], bS[NSTG];
    #pragma unroll
    for (int s = 0; s < NSTG; ++s) {
        uint32_t base = smem_u32(smemh + s * STG);
        aS[s] = base;
        bS[s] = base + ASZ * 2;
    }

    auto issue = [&](int kt, int s) {
        if (kt < DIM) {
            #pragma unroll
            for (int i = 0; i < 2; ++i) {
                int q = tid + i * 256;
                int r = q >> 2, c = (q & 3) * 8;
                uint32_t doff = (uint32_t)(r * ASTR + c) * 2;
                cpa16(aS[s] + doff, Qh + (long)(m0 + r) * DIM + kt + c);
                cpa16(bS[s] + doff, Kh + (long)(n0 + r) * DIM + kt + c);
            }
        }
        CP_COMMIT();
    };

    ACC_DECL();
    GEMM_MAINLOOP(DIM, active, true);

    if (active) {
        #pragma unroll
        for (int mt = 0; mt < 2; ++mt) {
            const int row = m0 + wm + mt * 16 + (lane >> 2);
            float mx0 = -3.0e38f, mx1 = -3.0e38f;
            #pragma unroll
            for (int nt = 0; nt < 8; ++nt) {
                const int col = n0 + wn + nt * 8 + (lane & 3) * 2;
                float* f = acc[mt][nt];
                *(float2*)(P + (long)row * SEQ + col) = make_float2(f[0], f[1]);
                *(float2*)(P + (long)(row + 8) * SEQ + col) =
                    make_float2(f[2], f[3]);
                // causal-masked per-row max
                if (!diag) {
                    mx0 = fmaxf(mx0, fmaxf(f[0], f[1]));
                    mx1 = fmaxf(mx1, fmaxf(f[2], f[3]));
                } else {
                    if (col     <= row)     mx0 = fmaxf(mx0, f[0]);
                    if (col + 1 <= row)     mx0 = fmaxf(mx0, f[1]);
                    if (col     <= row + 8) mx1 = fmaxf(mx1, f[2]);
                    if (col + 1 <= row + 8) mx1 = fmaxf(mx1, f[3]);
                }
            }
            // quad reduction: lanes 4q..4q+3 hold the same row pair
            #pragma unroll
            for (int o = 1; o < 4; o <<= 1) {
                mx0 = fmaxf(mx0, __shfl_xor_sync(0xffffffffu, mx0, o));
                mx1 = fmaxf(mx1, __shfl_xor_sync(0xffffffffu, mx1, o));
            }
            if ((lane & 3) == 0) {
                if (mx0 > -3.0e38f) atomicMax(&rm[row], fenc(mx0));
                if (mx1 > -3.0e38f) atomicMax(&rm[row + 8], fenc(mx1));
            }
        }
    }
}

// ---------------------------------------------------------------------------
// PV GEMM (NN fp16, K bounded): out = rs[row] * (P_e @ V), fp32 out.
// Longest-K tiles scheduled first (m0 reversed) for wave balance.
// ---------------------------------------------------------------------------
__global__ __launch_bounds__(256)
void gemm_pv(const __half* __restrict__ Ph, const __half* __restrict__ Vh,
             const float* __restrict__ rs, float* __restrict__ Out)
{
    constexpr int ASZ = 128 * ASTR;
    constexpr int BSZ = 32 * BSTR;
    constexpr int STG = ASZ + BSZ;
    extern __shared__ __half smemh[];

    const int m0 = (int)(gridDim.y - 1 - blockIdx.y) * 128;  // longest first
    const int n0 = blockIdx.x * 128;

    Ph += (long)blockIdx.z * SEQ * SEQ;
    Vh += (long)blockIdx.z * SEQ * DIM;
    rs += (long)blockIdx.z * SEQ;
    Out += (long)blockIdx.z * SEQ * DIM;

    const int tid  = threadIdx.x;
    const int lane = tid & 31;
    const int wm   = ((tid >> 5) & 3) * 32;
    const int wn   = (tid >> 7) * 64;
    const int kEnd = m0 + 128;   // P zero beyond diagonal tile edge

    uint32_t aS[NSTG], bS[NSTG];
    #pragma unroll
    for (int s = 0; s < NSTG; ++s) {
        uint32_t base = smem_u32(smemh + s * STG);
        aS[s] = base;
        bS[s] = base + ASZ * 2;
    }

    auto issue = [&](int kt, int s) {
        if (kt < kEnd) {
            #pragma unroll
            for (int i = 0; i < 2; ++i) {
                int q = tid + i * 256;
                int r = q >> 2, c = (q & 3) * 8;
                uint32_t doff = (uint32_t)(r * ASTR + c) * 2;
                cpa16(aS[s] + doff, Ph + (long)(m0 + r) * SEQ + kt + c);
                int kk = q >> 4, nn = (q & 15) * 8;
                uint32_t boff = (uint32_t)(kk * BSTR + nn) * 2;
                cpa16(bS[s] + boff, Vh + (long)(kt + kk) * DIM + n0 + nn);
            }
        }
        CP_COMMIT();
    };

    ACC_DECL();
    GEMM_MAINLOOP(kEnd, true, false);

    #pragma unroll
    for (int mt = 0; mt < 2; ++mt) {
        int row = m0 + wm + mt * 16 + (lane >> 2);
        float s0 = rs[row];
        float s1 = rs[row + 8];
        #pragma unroll
        for (int nt = 0; nt < 8; ++nt) {
            int col = n0 + wn + nt * 8 + (lane & 3) * 2;
            float* f = acc[mt][nt];
            *(float2*)(Out + (long)row * DIM + col) =
                make_float2(f[0] * s0, f[1] * s0);
            *(float2*)(Out + (long)(row + 8) * DIM + col) =
                make_float2(f[2] * s1, f[3] * s1);
        }
    }
}

// ---------------------------------------------------------------------------
// Causal softmax, SINGLE pass: row max comes precomputed from the scores
// epilogue. exp + fp16 store + sum; warp-shuffle reductions.
// ---------------------------------------------------------------------------
__device__ __forceinline__ float warp_sum(float v) {
    #pragma unroll
    for (int o = 16; o > 0; o >>= 1)
        v += __shfl_xor_sync(0xffffffffu, v, o);
    return v;
}

__global__ __launch_bounds__(256)
void softmax_causal(const float* __restrict__ P, const unsigned* __restrict__ rm,
                    __half* __restrict__ Ph, float* __restrict__ rs)
{
    const int S = SEQ;
    const int i = blockIdx.x, b = blockIdx.y;
    const float* row = P + ((long)b * S + i) * S;
    __half* hrow = Ph + ((long)b * S + i) * S;

    __shared__ float red[8];
    const int tid = threadIdx.x;
    const int lane = tid & 31;
    const int wid = tid >> 5;
    const int L = i + 1;
    const int full4 = L >> 2;
    const int kB = (i & ~127) + 128;

    const float m = fdec(rm[(long)b * S + i]) * SCALE;

    float sum = 0.f;
    for (int j4 = tid; j4 < full4; j4 += 256) {
        float4 v = *(const float4*)(row + j4 * 4);
        v.x = __expf(fmaf(v.x, SCALE, -m));
        v.y = __expf(fmaf(v.y, SCALE, -m));
        v.z = __expf(fmaf(v.z, SCALE, -m));
        v.w = __expf(fmaf(v.w, SCALE, -m));
        sum += v.x + v.y + v.z + v.w;
        __half2 h0 = __floats2half2_rn(v.x, v.y);
        __half2 h1 = __floats2half2_rn(v.z, v.w);
        uint2 u;
        u.x = reinterpret_cast<uint32_t&>(h0);
        u.y = reinterpret_cast<uint32_t&>(h1);
        *(uint2*)(hrow + j4 * 4) = u;
    }
    {
        int jb = full4 * 4 + tid;
        if (tid < (L & 3)) {
            float e = __expf(fmaf(row[jb], SCALE, -m));
            sum += e;
            hrow[jb] = __float2half_rn(e);
        }
    }
    for (int j = L + tid; j < kB; j += 256)
        hrow[j] = __float2half_rn(0.f);

    sum = warp_sum(sum);
    if (lane == 0) red[wid] = sum;
    __syncthreads();
    if (wid == 0) {
        float t = (lane < 8) ? red[lane] : 0.f;
        t = warp_sum(t);
        if (lane == 0) rs[(long)b * S + i] = 1.0f / t;
    }
}

// ---------------------------------------------------------------------------
extern "C" void kernel_launch(void* const* d_in, const int* in_sizes, int n_in,
                              void* d_out, int out_size)
{
    (void)in_sizes; (void)n_in; (void)out_size;
    const float* X  = (const float*)d_in[0];
    const float* Wq = (const float*)d_in[1];
    const float* Wk = (const float*)d_in[2];
    const float* Wv = (const float*)d_in[3];
    float* out = (float*)d_out;

    #define SYM(v, s) void* v; cudaGetSymbolAddress(&v, s)
    SYM(pP, g_P); SYM(pRs, g_rs); SYM(pRm, g_rm);
    SYM(pXh, g_Xh); SYM(pWh, g_Wh);
    SYM(pQh, g_Qh); SYM(pKh, g_Kh); SYM(pVh, g_Vh); SYM(pPh, g_Ph);
    #undef SYM

    const int NN_SMEM = NSTG * (128 * ASTR + 32 * BSTR) * 2;   // 56832 B
    const int NT_SMEM = NSTG * (2 * 128 * ASTR) * 2;           // 61440 B

    cudaFuncSetAttribute(gemm_qkv, cudaFuncAttributeMaxDynamicSharedMemorySize,
                         NN_SMEM);
    cudaFuncSetAttribute(gemm_scores, cudaFuncAttributeMaxDynamicSharedMemorySize,
                         NT_SMEM);
    cudaFuncSetAttribute(gemm_pv, cudaFuncAttributeMaxDynamicSharedMemorySize,
                         NN_SMEM);

    // 0) fused fp16 quantization of X, Wq, Wk, Wv + row-max init
    {
        long nX4 = (long)BATCH * SEQ * HID / 4;
        long nW4 = (long)HID * DIM / 4;
        quant_all<<<2960, 256>>>(X, Wq, Wk, Wv, (__half*)pXh, (__half*)pWh,
                                 (unsigned*)pRm, nX4, nW4);
    }

    // 1) merged QKV projections (fp16) -> fp16 Q, K, V
    {
        dim3 grid(24, (BATCH * SEQ) / 128, 1);
        gemm_qkv<<<grid, 256, NN_SMEM>>>(
            (__half*)pXh, (__half*)pWh,
            (__half*)pQh, (__half*)pKh, (__half*)pVh);
    }

    // 2) raw scores = Q @ K^T (fp16) + fused causal row-max atomics
    {
        dim3 grid(SEQ / 128, SEQ / 128, BATCH);
        gemm_scores<<<grid, 256, NT_SMEM>>>(
            (__half*)pQh, (__half*)pKh, (float*)pP, (unsigned*)pRm);
    }

    // 3) causal softmax (single pass, precomputed max)
    {
        dim3 grid(SEQ, BATCH);
        softmax_causal<<<grid, 256>>>((float*)pP, (unsigned*)pRm,
                                      (__half*)pPh, (float*)pRs);
    }

    // 4) out = rs * (P_e @ V), K bounded by causality, longest tiles first
    {
        dim3 grid(DIM / 128, SEQ / 128, BATCH);
        gemm_pv<<<grid, 256, NN_SMEM>>>(
            (__half*)pPh, (__half*)pVh, (float*)pRs, out);
    }
}